// round 9
// baseline (speedup 1.0000x reference)
#include <cuda_runtime.h>
#include <cuda_bf16.h>
#include <math.h>
#include <stdint.h>

typedef __nv_bfloat16 bf;

#define SEQ   2048
#define DM    1024
#define NH    16
#define HD    64
#define MROWS 4096
#define ZH    32

// ---------------------------------------------------------------------------
// Scratch (__device__ globals; no allocations allowed)
// ---------------------------------------------------------------------------
__device__ bf g_qh[MROWS*DM], g_ql[MROWS*DM];     // projected Q hi/lo (pre-scaled)
__device__ bf g_kh[MROWS*DM], g_kl[MROWS*DM];     // projected K hi/lo
__device__ bf g_vth[ZH*HD*SEQ], g_vtl[ZH*HD*SEQ]; // projected V^T per head hi/lo
__device__ bf g_ch[MROWS*DM], g_cl[MROWS*DM];     // context hi/lo

// ---------------------------------------------------------------------------
// PTX helpers (plain sm_103-legal: mma.sync / ldmatrix / cp.async)
// ---------------------------------------------------------------------------
__device__ __forceinline__ uint32_t su32(const void* p) {
    uint32_t a;
    asm("{ .reg .u64 t; cvta.to.shared.u64 t, %1; cvt.u32.u64 %0, t; }" : "=r"(a) : "l"(p));
    return a;
}
#define CPASYNC(d, s) asm volatile("cp.async.cg.shared.global [%0], [%1], 16;" :: "r"(d), "l"(s))
#define CPCOMMIT()    asm volatile("cp.async.commit_group;")
#define CPWAIT0()     asm volatile("cp.async.wait_group 0;")
#define CPWAIT1()     asm volatile("cp.async.wait_group 1;")

__device__ __forceinline__ void ldm4(uint32_t* r, uint32_t addr) {
    asm volatile("ldmatrix.sync.aligned.m8n8.x4.shared.b16 {%0,%1,%2,%3}, [%4];"
                 : "=r"(r[0]), "=r"(r[1]), "=r"(r[2]), "=r"(r[3]) : "r"(addr));
}
__device__ __forceinline__ void mma16816(float* c, const uint32_t* a, uint32_t b0, uint32_t b1) {
    asm volatile("mma.sync.aligned.m16n8k16.row.col.f32.bf16.bf16.f32 "
                 "{%0,%1,%2,%3}, {%4,%5,%6,%7}, {%8,%9}, {%0,%1,%2,%3};"
                 : "+f"(c[0]), "+f"(c[1]), "+f"(c[2]), "+f"(c[3])
                 : "r"(a[0]), "r"(a[1]), "r"(a[2]), "r"(a[3]), "r"(b0), "r"(b1));
}
__device__ __forceinline__ void bsplit(float x, bf& h, bf& l) {
    h = __float2bfloat16(x);
    l = __float2bfloat16(x - __bfloat162float(h));
}
__device__ __forceinline__ float bhi(float x) {
    return __bfloat162float(__float2bfloat16(x));
}
__device__ __forceinline__ uint32_t pk2(float lo, float hi) {   // {lo@0-15, hi@16-31}
    uint32_t r;
    asm("cvt.rn.bf16x2.f32 %0, %1, %2;" : "=r"(r) : "f"(hi), "f"(lo));
    return r;
}

#define GPL 5120   // elements per smem plane buffer (128 x 40)

// ---------------------------------------------------------------------------
// Fused Q/K/V projection GEMM, double-buffered smem, 1 sync per K-tile.
// C[4096,1024] = X @ W^T (+bias), 3-term split-bf16 MMA, in-kernel conversion.
// grid (8, 32, 3): z=0 Q (scaled), z=1 K, z=2 V (transposed). 80 KB dyn smem.
// ---------------------------------------------------------------------------
__global__ void __launch_bounds__(256, 1)
qkv_gemm(const float* __restrict__ xq, const float* __restrict__ xk,
         const float* __restrict__ xv,
         const float* __restrict__ wq, const float* __restrict__ wk,
         const float* __restrict__ wv,
         const float* __restrict__ bq, const float* __restrict__ bk,
         const float* __restrict__ bv,
         bf* __restrict__ qh, bf* __restrict__ ql,
         bf* __restrict__ kh, bf* __restrict__ kl,
         bf* __restrict__ vth, bf* __restrict__ vtl)
{
    extern __shared__ __align__(16) bf gsm[];
    bf* AH = gsm;            // [2][128][40]
    bf* AL = gsm + 2 * GPL;
    bf* BH = gsm + 4 * GPL;
    bf* BL = gsm + 6 * GPL;

    const int tid = threadIdx.x, lane = tid & 31, wid = tid >> 5;
    const int m0 = blockIdx.y * 128, n0 = blockIdx.x * 128, z = blockIdx.z;
    const float* X  = (z == 0) ? xq : (z == 1) ? xk : xv;
    const float* W  = (z == 0) ? wq : (z == 1) ? wk : wv;
    const float* Bi = (z == 0) ? bq : (z == 1) ? bk : bv;

    const int lr = tid >> 3, lc = (tid & 7) * 4;   // 4 rows per 256-thr pass

    float ar[16], br[16];
    auto ldg = [&](int kb) {
        #pragma unroll
        for (int i = 0; i < 4; i++) {
            int r = lr + 32 * i;
            *(float4*)(ar + 4 * i) = *(const float4*)(X + (size_t)(m0 + r) * DM + kb + lc);
            *(float4*)(br + 4 * i) = *(const float4*)(W + (size_t)(n0 + r) * DM + kb + lc);
        }
    };
    auto sts = [&](int st) {
        bf* ah = AH + st * GPL; bf* al = AL + st * GPL;
        bf* bh = BH + st * GPL; bf* bl = BL + st * GPL;
        #pragma unroll
        for (int i = 0; i < 4; i++) {
            int r = lr + 32 * i;
            #pragma unroll
            for (int u = 0; u < 4; u += 2) {
                bf h0, l0, h1, l1;
                bsplit(ar[4 * i + u], h0, l0); bsplit(ar[4 * i + u + 1], h1, l1);
                *(__nv_bfloat162*)&ah[r * 40 + lc + u] = __nv_bfloat162(h0, h1);
                *(__nv_bfloat162*)&al[r * 40 + lc + u] = __nv_bfloat162(l0, l1);
                bsplit(br[4 * i + u], h0, l0); bsplit(br[4 * i + u + 1], h1, l1);
                *(__nv_bfloat162*)&bh[r * 40 + lc + u] = __nv_bfloat162(h0, h1);
                *(__nv_bfloat162*)&bl[r * 40 + lc + u] = __nv_bfloat162(l0, l1);
            }
        }
    };

    const int wm = wid >> 1, wn = wid & 1;
    float acc[2][8][4];
    #pragma unroll
    for (int i = 0; i < 2; i++)
        #pragma unroll
        for (int j = 0; j < 8; j++)
            #pragma unroll
            for (int t = 0; t < 4; t++) acc[i][j][t] = 0.f;

    const int frow = ((lane >> 3) & 1) * 8 + (lane & 7);
    const int fcol = ((lane >> 4) & 1) * 8;

    ldg(0); sts(0); ldg(32);
    __syncthreads();

    for (int kt = 0; kt < 32; kt++) {
        const int st = kt & 1;
        const bf* ah = AH + st * GPL; const bf* al = AL + st * GPL;
        const bf* bh = BH + st * GPL; const bf* bl = BL + st * GPL;

        // k16 = 0 MMAs
        #pragma unroll
        for (int k16 = 0; k16 < 2; k16++) {
            uint32_t a_h[2][4], a_l[2][4];
            #pragma unroll
            for (int i = 0; i < 2; i++) {
                ldm4(a_h[i], su32(&ah[(wm * 32 + i * 16 + frow) * 40 + k16 * 16 + fcol]));
                ldm4(a_l[i], su32(&al[(wm * 32 + i * 16 + frow) * 40 + k16 * 16 + fcol]));
            }
            #pragma unroll
            for (int j = 0; j < 4; j++) {
                uint32_t b_h[4], b_l[4];
                ldm4(b_h, su32(&bh[(wn * 64 + j * 16 + frow) * 40 + k16 * 16 + fcol]));
                ldm4(b_l, su32(&bl[(wn * 64 + j * 16 + frow) * 40 + k16 * 16 + fcol]));
                #pragma unroll
                for (int i = 0; i < 2; i++) {
                    mma16816(acc[i][2 * j],     a_h[i], b_h[0], b_h[2]);
                    mma16816(acc[i][2 * j + 1], a_h[i], b_h[1], b_h[3]);
                    mma16816(acc[i][2 * j],     a_l[i], b_h[0], b_h[2]);
                    mma16816(acc[i][2 * j + 1], a_l[i], b_h[1], b_h[3]);
                    mma16816(acc[i][2 * j],     a_h[i], b_l[0], b_l[2]);
                    mma16816(acc[i][2 * j + 1], a_h[i], b_l[1], b_l[3]);
                }
            }
            // overlap: after first k16 pass, store tile kt+1 and prefetch kt+2
            if (k16 == 0 && kt < 31) {
                sts(st ^ 1);
                if (kt < 30) ldg((kt + 2) * 32);
            }
        }
        __syncthreads();
    }

    const int er = lane >> 2, ec = (lane & 3) * 2;
    #pragma unroll
    for (int i = 0; i < 2; i++) {
        #pragma unroll
        for (int j = 0; j < 8; j++) {
            #pragma unroll
            for (int h2 = 0; h2 < 2; h2++) {
                int rr = m0 + wm * 32 + i * 16 + er + h2 * 8;
                int nb = n0 + wn * 64 + j * 8 + ec;
                #pragma unroll
                for (int t = 0; t < 2; t++) {
                    int n = nb + t;
                    float x = acc[i][j][h2 * 2 + t] + Bi[n];
                    bf hi, lo;
                    if (z == 0) {
                        x *= 0.125f;
                        bsplit(x, hi, lo);
                        qh[(size_t)rr * DM + n] = hi; ql[(size_t)rr * DM + n] = lo;
                    } else if (z == 1) {
                        bsplit(x, hi, lo);
                        kh[(size_t)rr * DM + n] = hi; kl[(size_t)rr * DM + n] = lo;
                    } else {
                        int hh = n >> 6, d = n & 63;
                        int zz = (rr >> 11) * NH + hh, s = rr & 2047;
                        size_t base = (size_t)zz * HD * SEQ + (size_t)d * SEQ + s;
                        bsplit(x, hi, lo);
                        vth[base] = hi; vtl[base] = lo;
                    }
                }
            }
        }
    }
}

// ---------------------------------------------------------------------------
// Output projection, same double-buffered skeleton. ctx hi/lo planes in,
// wo fp32 converted in-kernel, fp32 out.
// ---------------------------------------------------------------------------
__global__ void __launch_bounds__(256, 1)
oproj_gemm(const bf* __restrict__ Ch, const bf* __restrict__ Cl,
           const float* __restrict__ W, const float* __restrict__ Bi,
           float* __restrict__ Out)
{
    extern __shared__ __align__(16) bf gsm[];
    bf* AH = gsm;
    bf* AL = gsm + 2 * GPL;
    bf* BH = gsm + 4 * GPL;
    bf* BL = gsm + 6 * GPL;

    const int tid = threadIdx.x, lane = tid & 31, wid = tid >> 5;
    const int m0 = blockIdx.y * 128, n0 = blockIdx.x * 128;
    const int lr = tid >> 3, lc = (tid & 7) * 4;

    uint2 arh[4], arl[4];
    float br[16];
    auto ldg = [&](int kb) {
        #pragma unroll
        for (int i = 0; i < 4; i++) {
            int r = lr + 32 * i;
            arh[i] = *(const uint2*)(Ch + (size_t)(m0 + r) * DM + kb + lc);
            arl[i] = *(const uint2*)(Cl + (size_t)(m0 + r) * DM + kb + lc);
            *(float4*)(br + 4 * i) = *(const float4*)(W + (size_t)(n0 + r) * DM + kb + lc);
        }
    };
    auto sts = [&](int st) {
        bf* ah = AH + st * GPL; bf* al = AL + st * GPL;
        bf* bh = BH + st * GPL; bf* bl = BL + st * GPL;
        #pragma unroll
        for (int i = 0; i < 4; i++) {
            int r = lr + 32 * i;
            *(uint2*)&ah[r * 40 + lc] = arh[i];
            *(uint2*)&al[r * 40 + lc] = arl[i];
            #pragma unroll
            for (int u = 0; u < 4; u += 2) {
                bf h0, l0, h1, l1;
                bsplit(br[4 * i + u], h0, l0); bsplit(br[4 * i + u + 1], h1, l1);
                *(__nv_bfloat162*)&bh[r * 40 + lc + u] = __nv_bfloat162(h0, h1);
                *(__nv_bfloat162*)&bl[r * 40 + lc + u] = __nv_bfloat162(l0, l1);
            }
        }
    };

    const int wm = wid >> 1, wn = wid & 1;
    float acc[2][8][4];
    #pragma unroll
    for (int i = 0; i < 2; i++)
        #pragma unroll
        for (int j = 0; j < 8; j++)
            #pragma unroll
            for (int t = 0; t < 4; t++) acc[i][j][t] = 0.f;

    const int frow = ((lane >> 3) & 1) * 8 + (lane & 7);
    const int fcol = ((lane >> 4) & 1) * 8;

    ldg(0); sts(0); ldg(32);
    __syncthreads();

    for (int kt = 0; kt < 32; kt++) {
        const int st = kt & 1;
        const bf* ah = AH + st * GPL; const bf* al = AL + st * GPL;
        const bf* bh = BH + st * GPL; const bf* bl = BL + st * GPL;

        #pragma unroll
        for (int k16 = 0; k16 < 2; k16++) {
            uint32_t a_h[2][4], a_l[2][4];
            #pragma unroll
            for (int i = 0; i < 2; i++) {
                ldm4(a_h[i], su32(&ah[(wm * 32 + i * 16 + frow) * 40 + k16 * 16 + fcol]));
                ldm4(a_l[i], su32(&al[(wm * 32 + i * 16 + frow) * 40 + k16 * 16 + fcol]));
            }
            #pragma unroll
            for (int j = 0; j < 4; j++) {
                uint32_t b_h[4], b_l[4];
                ldm4(b_h, su32(&bh[(wn * 64 + j * 16 + frow) * 40 + k16 * 16 + fcol]));
                ldm4(b_l, su32(&bl[(wn * 64 + j * 16 + frow) * 40 + k16 * 16 + fcol]));
                #pragma unroll
                for (int i = 0; i < 2; i++) {
                    mma16816(acc[i][2 * j],     a_h[i], b_h[0], b_h[2]);
                    mma16816(acc[i][2 * j + 1], a_h[i], b_h[1], b_h[3]);
                    mma16816(acc[i][2 * j],     a_l[i], b_h[0], b_h[2]);
                    mma16816(acc[i][2 * j + 1], a_l[i], b_h[1], b_h[3]);
                    mma16816(acc[i][2 * j],     a_h[i], b_l[0], b_l[2]);
                    mma16816(acc[i][2 * j + 1], a_h[i], b_l[1], b_l[3]);
                }
            }
            if (k16 == 0 && kt < 31) {
                sts(st ^ 1);
                if (kt < 30) ldg((kt + 2) * 32);
            }
        }
        __syncthreads();
    }

    const int er = lane >> 2, ec = (lane & 3) * 2;
    #pragma unroll
    for (int i = 0; i < 2; i++) {
        #pragma unroll
        for (int j = 0; j < 8; j++) {
            #pragma unroll
            for (int h2 = 0; h2 < 2; h2++) {
                int rr = m0 + wm * 32 + i * 16 + er + h2 * 8;
                int nb = n0 + wn * 64 + j * 8 + ec;
                Out[(size_t)rr * DM + nb]     = acc[i][j][h2 * 2 + 0] + Bi[nb];
                Out[(size_t)rr * DM + nb + 1] = acc[i][j][h2 * 2 + 1] + Bi[nb + 1];
            }
        }
    }
}

// ---------------------------------------------------------------------------
// Fused flash attention (planar hi/lo). Block = 128 queries x 1 head.
// Q/K smem tiles: cols 0-63 hi, 64-127 lo. S = QhKh + QlKh + QhKl.
// PV = Ph·Vh + Pl·Vh + Ph·Vl. ctx written as hi/lo planes.
// ---------------------------------------------------------------------------
#define FA_QS    0
#define FA_KS    17408                    // Q: 128 x 136
#define FA_VS    34816                    // K: 2 buf x 64 x 136
#define FA_MSK_B 106496                   // after V: 2 buf x 2 planes x 64 x 72
#define FA_FLG_B 114688
#define FA_SMEM  114816

__global__ void __launch_bounds__(256, 1)
flash_attn(const bf* __restrict__ Qh, const bf* __restrict__ Ql,
           const bf* __restrict__ Kh, const bf* __restrict__ Kl,
           const bf* __restrict__ Vh, const bf* __restrict__ Vl,
           const int* __restrict__ mask,
           bf* __restrict__ Ch, bf* __restrict__ Cl)
{
    extern __shared__ __align__(16) bf sm[];
    bf* Qs = sm + FA_QS;
    bf* Ks = sm + FA_KS;
    bf* Vs = sm + FA_VS;
    int* msk = (int*)((char*)sm + FA_MSK_B);
    int* flg = (int*)((char*)sm + FA_FLG_B);

    const int tid = threadIdx.x, lane = tid & 31, w = tid >> 5;
    const int qb = blockIdx.x, z = blockIdx.y;
    const int b = z >> 4, h = z & 15;

    const bf* Qhp = Qh + ((size_t)(b * SEQ + qb * 128)) * DM + h * HD;
    const bf* Qlp = Ql + ((size_t)(b * SEQ + qb * 128)) * DM + h * HD;
    const bf* Khp = Kh + ((size_t)(b * SEQ)) * DM + h * HD;
    const bf* Klp = Kl + ((size_t)(b * SEQ)) * DM + h * HD;
    const bf* Vhp = Vh + (size_t)z * HD * SEQ;
    const bf* Vlp = Vl + (size_t)z * HD * SEQ;

    if (tid < 32) flg[tid] = 0;
    __syncthreads();
    #pragma unroll
    for (int i = 0; i < 8; i++) {
        int k = tid + i * 256;
        int m = mask[b * SEQ + k];
        msk[k] = m;
        if (m == 0) flg[k >> 6] = 1;
    }

    // Q tile: 128 rows x (64 hi | 64 lo)
    {
        int r = tid >> 1, q = tid & 1;
        #pragma unroll
        for (int i = 0; i < 4; i++) {
            int cc = (q + i * 2) * 8;
            CPASYNC(su32(Qs + r * 136 + cc),      Qhp + (size_t)r * DM + cc);
            CPASYNC(su32(Qs + r * 136 + 64 + cc), Qlp + (size_t)r * DM + cc);
        }
    }
    auto loadKV = [&](int kb, int st) {
        int r = tid >> 2, q = tid & 3;
        #pragma unroll
        for (int i = 0; i < 2; i++) {
            int cc = (q + i * 4) * 8;
            CPASYNC(su32(Ks + st * 8704 + r * 136 + cc),
                    Khp + (size_t)(kb * 64 + r) * DM + cc);
            CPASYNC(su32(Ks + st * 8704 + r * 136 + 64 + cc),
                    Klp + (size_t)(kb * 64 + r) * DM + cc);
            CPASYNC(su32(Vs + st * 9216 + r * 72 + cc),
                    Vhp + (size_t)r * SEQ + kb * 64 + cc);
            CPASYNC(su32(Vs + st * 9216 + 4608 + r * 72 + cc),
                    Vlp + (size_t)r * SEQ + kb * 64 + cc);
        }
    };
    loadKV(0, 0); CPCOMMIT();

    const int frow = ((lane >> 3) & 1) * 8 + (lane & 7);
    const int fcol = ((lane >> 4) & 1) * 8;
    const int er = lane >> 2, ec = (lane & 3) * 2;

    uint32_t qf[8][4];
    float Oa[8][4];
    #pragma unroll
    for (int j = 0; j < 8; j++)
        #pragma unroll
        for (int t = 0; t < 4; t++) Oa[j][t] = 0.f;
    float mrow[2] = { -1e30f, -1e30f }, lrow[2] = { 0.f, 0.f };

    for (int kb = 0; kb < 32; kb++) {
        const int st = kb & 1;
        if (kb + 1 < 32) { loadKV(kb + 1, st ^ 1); CPCOMMIT(); CPWAIT1(); }
        else             { CPWAIT0(); }
        __syncthreads();
        if (kb == 0) {
            #pragma unroll
            for (int k16 = 0; k16 < 8; k16++)
                ldm4(qf[k16], su32(Qs + (w * 16 + frow) * 136 + k16 * 16 + fcol));
        }

        // ---- S = QhKh + QlKh + QhKl (16 x 64 per warp) ----
        float Sa[8][4];
        #pragma unroll
        for (int j = 0; j < 8; j++)
            #pragma unroll
            for (int t = 0; t < 4; t++) Sa[j][t] = 0.f;

        const bf* kbuf = Ks + st * 8704;
        #pragma unroll
        for (int j = 0; j < 4; j++) {
            #pragma unroll
            for (int k = 0; k < 4; k++) {
                uint32_t bh4[4], bl4[4];
                ldm4(bh4, su32(kbuf + (j * 16 + frow) * 136 + k * 16 + fcol));
                ldm4(bl4, su32(kbuf + (j * 16 + frow) * 136 + (k + 4) * 16 + fcol));
                mma16816(Sa[2 * j],     qf[k],     bh4[0], bh4[2]);
                mma16816(Sa[2 * j + 1], qf[k],     bh4[1], bh4[3]);
                mma16816(Sa[2 * j],     qf[k + 4], bh4[0], bh4[2]);
                mma16816(Sa[2 * j + 1], qf[k + 4], bh4[1], bh4[3]);
                mma16816(Sa[2 * j],     qf[k],     bl4[0], bl4[2]);
                mma16816(Sa[2 * j + 1], qf[k],     bl4[1], bl4[3]);
            }
        }

        // ---- mask ----
        if (flg[kb]) {
            #pragma unroll
            for (int j = 0; j < 8; j++) {
                int c0 = kb * 64 + j * 8 + ec;
                if (!msk[c0])     { Sa[j][0] = -1e9f; Sa[j][2] = -1e9f; }
                if (!msk[c0 + 1]) { Sa[j][1] = -1e9f; Sa[j][3] = -1e9f; }
            }
        }

        // ---- online softmax (rows er, er+8) ----
        float mx0 = -1e30f, mx1 = -1e30f;
        #pragma unroll
        for (int j = 0; j < 8; j++) {
            mx0 = fmaxf(mx0, fmaxf(Sa[j][0], Sa[j][1]));
            mx1 = fmaxf(mx1, fmaxf(Sa[j][2], Sa[j][3]));
        }
        #pragma unroll
        for (int o = 1; o <= 2; o <<= 1) {
            mx0 = fmaxf(mx0, __shfl_xor_sync(0xffffffffu, mx0, o));
            mx1 = fmaxf(mx1, __shfl_xor_sync(0xffffffffu, mx1, o));
        }
        float nm0 = fmaxf(mrow[0], mx0), nm1 = fmaxf(mrow[1], mx1);
        float cor0 = __expf(mrow[0] - nm0), cor1 = __expf(mrow[1] - nm1);
        mrow[0] = nm0; mrow[1] = nm1;

        float rs0 = 0.f, rs1 = 0.f;
        #pragma unroll
        for (int j = 0; j < 8; j++) {
            Sa[j][0] = __expf(Sa[j][0] - nm0); rs0 += Sa[j][0];
            Sa[j][1] = __expf(Sa[j][1] - nm0); rs0 += Sa[j][1];
            Sa[j][2] = __expf(Sa[j][2] - nm1); rs1 += Sa[j][2];
            Sa[j][3] = __expf(Sa[j][3] - nm1); rs1 += Sa[j][3];
        }
        #pragma unroll
        for (int o = 1; o <= 2; o <<= 1) {
            rs0 += __shfl_xor_sync(0xffffffffu, rs0, o);
            rs1 += __shfl_xor_sync(0xffffffffu, rs1, o);
        }
        lrow[0] = lrow[0] * cor0 + rs0;
        lrow[1] = lrow[1] * cor1 + rs1;
        #pragma unroll
        for (int j = 0; j < 8; j++) {
            Oa[j][0] *= cor0; Oa[j][1] *= cor0;
            Oa[j][2] *= cor1; Oa[j][3] *= cor1;
        }

        // ---- PV: O += Ph·Vh + Pl·Vh + Ph·Vl ----
        const bf* vh = Vs + st * 9216;
        const bf* vl = vh + 4608;
        #pragma unroll
        for (int c = 0; c < 4; c++) {
            float a0 = Sa[2*c][0], a1 = Sa[2*c][1], a2 = Sa[2*c][2], a3 = Sa[2*c][3];
            float b0 = Sa[2*c+1][0], b1 = Sa[2*c+1][1], b2 = Sa[2*c+1][2], b3 = Sa[2*c+1][3];
            uint32_t ph[4], pl[4];
            ph[0] = pk2(a0, a1); ph[1] = pk2(a2, a3);
            ph[2] = pk2(b0, b1); ph[3] = pk2(b2, b3);
            pl[0] = pk2(a0 - bhi(a0), a1 - bhi(a1));
            pl[1] = pk2(a2 - bhi(a2), a3 - bhi(a3));
            pl[2] = pk2(b0 - bhi(b0), b1 - bhi(b1));
            pl[3] = pk2(b2 - bhi(b2), b3 - bhi(b3));
            #pragma unroll
            for (int t = 0; t < 4; t++) {
                uint32_t bh4[4], bl4[4];
                ldm4(bh4, su32(vh + (t * 16 + frow) * 72 + c * 16 + fcol));
                ldm4(bl4, su32(vl + (t * 16 + frow) * 72 + c * 16 + fcol));
                mma16816(Oa[2 * t],     ph, bh4[0], bh4[2]);
                mma16816(Oa[2 * t + 1], ph, bh4[1], bh4[3]);
                mma16816(Oa[2 * t],     pl, bh4[0], bh4[2]);
                mma16816(Oa[2 * t + 1], pl, bh4[1], bh4[3]);
                mma16816(Oa[2 * t],     ph, bl4[0], bl4[2]);
                mma16816(Oa[2 * t + 1], ph, bl4[1], bl4[3]);
            }
        }
        __syncthreads();
    }

    // ---- epilogue: normalize, write ctx hi/lo planes ----
    float i0 = 1.f / lrow[0], i1 = 1.f / lrow[1];
    int r0g = b * SEQ + qb * 128 + w * 16 + er;
    size_t base0 = (size_t)r0g * DM + h * HD;
    size_t base1 = base0 + (size_t)8 * DM;
    #pragma unroll
    for (int j = 0; j < 8; j++) {
        int d0 = j * 8 + ec;
        float v00 = Oa[j][0] * i0, v01 = Oa[j][1] * i0;
        float v10 = Oa[j][2] * i1, v11 = Oa[j][3] * i1;
        bf h00, l00, h01, l01, h10, l10, h11, l11;
        bsplit(v00, h00, l00); bsplit(v01, h01, l01);
        bsplit(v10, h10, l10); bsplit(v11, h11, l11);
        *(__nv_bfloat162*)(Ch + base0 + d0) = __nv_bfloat162(h00, h01);
        *(__nv_bfloat162*)(Cl + base0 + d0) = __nv_bfloat162(l00, l01);
        *(__nv_bfloat162*)(Ch + base1 + d0) = __nv_bfloat162(h10, h11);
        *(__nv_bfloat162*)(Cl + base1 + d0) = __nv_bfloat162(l10, l11);
    }
}

// ---------------------------------------------------------------------------
extern "C" void kernel_launch(void* const* d_in, const int* in_sizes, int n_in,
                              void* d_out, int out_size)
{
    const float* query = (const float*)d_in[0];
    const float* key   = (const float*)d_in[1];
    const float* value = (const float*)d_in[2];
    const int*   mask  = (const int*)d_in[3];
    const float* wq = (const float*)d_in[4];  const float* bq = (const float*)d_in[5];
    const float* wk = (const float*)d_in[6];  const float* bk = (const float*)d_in[7];
    const float* wv = (const float*)d_in[8];  const float* bv = (const float*)d_in[9];
    const float* wo = (const float*)d_in[10]; const float* bo = (const float*)d_in[11];

    #define SYM(p, sname) void* p; cudaGetSymbolAddress(&p, sname)
    SYM(qh, g_qh); SYM(ql, g_ql); SYM(kh, g_kh); SYM(kl, g_kl);
    SYM(vth, g_vth); SYM(vtl, g_vtl); SYM(ch, g_ch); SYM(cl, g_cl);
    #undef SYM

    const int GEMM_SMEM = 8 * GPL * (int)sizeof(bf);   // 81920
    static bool init = false;
    if (!init) {
        cudaFuncSetAttribute(flash_attn, cudaFuncAttributeMaxDynamicSharedMemorySize,
                             FA_SMEM);
        cudaFuncSetAttribute(qkv_gemm, cudaFuncAttributeMaxDynamicSharedMemorySize,
                             GEMM_SMEM);
        cudaFuncSetAttribute(oproj_gemm, cudaFuncAttributeMaxDynamicSharedMemorySize,
                             GEMM_SMEM);
        init = true;
    }

    qkv_gemm<<<dim3(8, 32, 3), 256, GEMM_SMEM>>>(
        query, key, value, wq, wk, wv, bq, bk, bv,
        (bf*)qh, (bf*)ql, (bf*)kh, (bf*)kl, (bf*)vth, (bf*)vtl);

    flash_attn<<<dim3(SEQ / 128, ZH), 256, FA_SMEM>>>(
        (bf*)qh, (bf*)ql, (bf*)kh, (bf*)kl, (bf*)vth, (bf*)vtl, mask,
        (bf*)ch, (bf*)cl);

    oproj_gemm<<<dim3(8, 32), 256, GEMM_SMEM>>>((bf*)ch, (bf*)cl, wo, bo, (float*)d_out);
}

// round 10
// speedup vs baseline: 1.0253x; 1.0253x over previous
#include <cuda_runtime.h>
#include <cuda_bf16.h>
#include <math.h>
#include <stdint.h>

typedef __nv_bfloat16 bf;

#define SEQ   2048
#define DM    1024
#define NH    16
#define HD    64
#define MROWS 4096
#define ZH    32
#define NELEM (MROWS*DM)      // 4M
#define WELEM (DM*DM)         // 1M

// ---------------------------------------------------------------------------
// Scratch (__device__ globals; no allocations allowed)
// ---------------------------------------------------------------------------
__device__ bf g_xh[3*NELEM], g_xl[3*NELEM];        // split inputs (q,k,v)
__device__ bf g_wph[4*WELEM], g_wpl[4*WELEM];      // split weights (wq,wk,wv,wo)
__device__ bf g_qh[NELEM], g_ql[NELEM];            // projected Q hi/lo (pre-scaled)
__device__ bf g_kh[NELEM], g_kl[NELEM];            // projected K hi/lo
__device__ bf g_vth[ZH*HD*SEQ], g_vtl[ZH*HD*SEQ];  // projected V^T per head hi/lo
__device__ bf g_ch[NELEM], g_cl[NELEM];            // context hi/lo

// ---------------------------------------------------------------------------
// PTX helpers (plain sm_103-legal: mma.sync / ldmatrix / cp.async)
// ---------------------------------------------------------------------------
__device__ __forceinline__ uint32_t su32(const void* p) {
    uint32_t a;
    asm("{ .reg .u64 t; cvta.to.shared.u64 t, %1; cvt.u32.u64 %0, t; }" : "=r"(a) : "l"(p));
    return a;
}
#define CPASYNC(d, s) asm volatile("cp.async.cg.shared.global [%0], [%1], 16;" :: "r"(d), "l"(s))
#define CPCOMMIT()    asm volatile("cp.async.commit_group;")
#define CPWAIT0()     asm volatile("cp.async.wait_group 0;")
#define CPWAIT1()     asm volatile("cp.async.wait_group 1;")

__device__ __forceinline__ void ldm4(uint32_t* r, uint32_t addr) {
    asm volatile("ldmatrix.sync.aligned.m8n8.x4.shared.b16 {%0,%1,%2,%3}, [%4];"
                 : "=r"(r[0]), "=r"(r[1]), "=r"(r[2]), "=r"(r[3]) : "r"(addr));
}
__device__ __forceinline__ void mma16816(float* c, const uint32_t* a, uint32_t b0, uint32_t b1) {
    asm volatile("mma.sync.aligned.m16n8k16.row.col.f32.bf16.bf16.f32 "
                 "{%0,%1,%2,%3}, {%4,%5,%6,%7}, {%8,%9}, {%0,%1,%2,%3};"
                 : "+f"(c[0]), "+f"(c[1]), "+f"(c[2]), "+f"(c[3])
                 : "r"(a[0]), "r"(a[1]), "r"(a[2]), "r"(a[3]), "r"(b0), "r"(b1));
}
__device__ __forceinline__ void bsplit(float x, bf& h, bf& l) {
    h = __float2bfloat16(x);
    l = __float2bfloat16(x - __bfloat162float(h));
}
__device__ __forceinline__ float bhi(float x) {
    return __bfloat162float(__float2bfloat16(x));
}
__device__ __forceinline__ uint32_t pk2(float lo, float hi) {   // {lo@0-15, hi@16-31}
    uint32_t r;
    asm("cvt.rn.bf16x2.f32 %0, %1, %2;" : "=r"(r) : "f"(hi), "f"(lo));
    return r;
}

// ---------------------------------------------------------------------------
// fp32 -> planar bf16 hi/lo split (vectorized, streaming)
// ---------------------------------------------------------------------------
__global__ void __launch_bounds__(256)
split_pair(const float4* __restrict__ in, uint2* __restrict__ hi,
           uint2* __restrict__ lo, int n4)
{
    int i = blockIdx.x * 256 + threadIdx.x;
    if (i >= n4) return;
    float4 v = in[i];
    float hx = bhi(v.x), hy = bhi(v.y), hz = bhi(v.z), hw = bhi(v.w);
    uint2 h, l;
    h.x = pk2(v.x, v.y);           h.y = pk2(v.z, v.w);
    l.x = pk2(v.x - hx, v.y - hy); l.y = pk2(v.z - hz, v.w - hw);
    hi[i] = h; lo[i] = l;
}

#define GPL 5120   // elements per smem plane buffer (128 x 40)

// ---------------------------------------------------------------------------
// Pure-bf16 split GEMM: C[M,1024] = A @ B^T (+bias), 3-term split MMA.
// All operands pre-split planar hi/lo; cp.async double-buffered; 2 CTAs/SM.
// QKV=1: grid (8,32,3), z selects Q/K/V input+weight, mode epilogues.
// QKV=0: out-projection (A=ctx planes, B=wo planes, fp32 out).
// ---------------------------------------------------------------------------
template<int QKV>
__global__ void __launch_bounds__(256, 2)
gemm_bf(const bf* __restrict__ Xh, const bf* __restrict__ Xl,
        const bf* __restrict__ Wh, const bf* __restrict__ Wl,
        const float* __restrict__ bq, const float* __restrict__ bk,
        const float* __restrict__ bv,
        float* __restrict__ Outf,
        bf* __restrict__ qh, bf* __restrict__ ql,
        bf* __restrict__ kh, bf* __restrict__ kl,
        bf* __restrict__ vth, bf* __restrict__ vtl)
{
    extern __shared__ __align__(16) bf gsm[];
    bf* AH = gsm;            // [2][128][40]
    bf* AL = gsm + 2 * GPL;
    bf* BH = gsm + 4 * GPL;
    bf* BL = gsm + 6 * GPL;

    const int tid = threadIdx.x, lane = tid & 31, wid = tid >> 5;
    const int m0 = blockIdx.y * 128, n0 = blockIdx.x * 128;
    const int z = QKV ? blockIdx.z : 0;

    const bf* Ahp = Xh + (QKV ? (size_t)z * NELEM : 0) + (size_t)m0 * DM;
    const bf* Alp = Xl + (QKV ? (size_t)z * NELEM : 0) + (size_t)m0 * DM;
    const bf* Bhp = Wh + (QKV ? (size_t)z * WELEM : 0) + (size_t)n0 * DM;
    const bf* Blp = Wl + (QKV ? (size_t)z * WELEM : 0) + (size_t)n0 * DM;
    const float* Bi = QKV ? ((z == 0) ? bq : (z == 1) ? bk : bv) : bq;

    auto loadTile = [&](int kt, int st) {
        const int kb = kt * 32;
        const int r = tid >> 1, c0 = (tid & 1) * 16;
        bf* ah = AH + st * GPL; bf* al = AL + st * GPL;
        bf* bh = BH + st * GPL; bf* bl = BL + st * GPL;
        CPASYNC(su32(&ah[r * 40 + c0]),     Ahp + (size_t)r * DM + kb + c0);
        CPASYNC(su32(&ah[r * 40 + c0 + 8]), Ahp + (size_t)r * DM + kb + c0 + 8);
        CPASYNC(su32(&al[r * 40 + c0]),     Alp + (size_t)r * DM + kb + c0);
        CPASYNC(su32(&al[r * 40 + c0 + 8]), Alp + (size_t)r * DM + kb + c0 + 8);
        CPASYNC(su32(&bh[r * 40 + c0]),     Bhp + (size_t)r * DM + kb + c0);
        CPASYNC(su32(&bh[r * 40 + c0 + 8]), Bhp + (size_t)r * DM + kb + c0 + 8);
        CPASYNC(su32(&bl[r * 40 + c0]),     Blp + (size_t)r * DM + kb + c0);
        CPASYNC(su32(&bl[r * 40 + c0 + 8]), Blp + (size_t)r * DM + kb + c0 + 8);
    };

    const int wm = wid >> 1, wn = wid & 1;
    float acc[2][8][4];
    #pragma unroll
    for (int i = 0; i < 2; i++)
        #pragma unroll
        for (int j = 0; j < 8; j++)
            #pragma unroll
            for (int t = 0; t < 4; t++) acc[i][j][t] = 0.f;

    const int frow = ((lane >> 3) & 1) * 8 + (lane & 7);
    const int fcol = ((lane >> 4) & 1) * 8;

    loadTile(0, 0); CPCOMMIT();

    for (int kt = 0; kt < 32; kt++) {
        const int st = kt & 1;
        if (kt < 31) { loadTile(kt + 1, st ^ 1); CPCOMMIT(); CPWAIT1(); }
        else         { CPWAIT0(); }
        __syncthreads();

        const bf* ah = AH + st * GPL; const bf* al = AL + st * GPL;
        const bf* bh = BH + st * GPL; const bf* bl = BL + st * GPL;
        #pragma unroll
        for (int k16 = 0; k16 < 2; k16++) {
            uint32_t a_h[2][4], a_l[2][4];
            #pragma unroll
            for (int i = 0; i < 2; i++) {
                ldm4(a_h[i], su32(&ah[(wm * 32 + i * 16 + frow) * 40 + k16 * 16 + fcol]));
                ldm4(a_l[i], su32(&al[(wm * 32 + i * 16 + frow) * 40 + k16 * 16 + fcol]));
            }
            #pragma unroll
            for (int j = 0; j < 4; j++) {
                uint32_t b_h[4], b_l[4];
                ldm4(b_h, su32(&bh[(wn * 64 + j * 16 + frow) * 40 + k16 * 16 + fcol]));
                ldm4(b_l, su32(&bl[(wn * 64 + j * 16 + frow) * 40 + k16 * 16 + fcol]));
                #pragma unroll
                for (int i = 0; i < 2; i++) {
                    mma16816(acc[i][2 * j],     a_h[i], b_h[0], b_h[2]);
                    mma16816(acc[i][2 * j + 1], a_h[i], b_h[1], b_h[3]);
                    mma16816(acc[i][2 * j],     a_l[i], b_h[0], b_h[2]);
                    mma16816(acc[i][2 * j + 1], a_l[i], b_h[1], b_h[3]);
                    mma16816(acc[i][2 * j],     a_h[i], b_l[0], b_l[2]);
                    mma16816(acc[i][2 * j + 1], a_h[i], b_l[1], b_l[3]);
                }
            }
        }
        __syncthreads();
    }

    const int er = lane >> 2, ec = (lane & 3) * 2;
    #pragma unroll
    for (int i = 0; i < 2; i++) {
        #pragma unroll
        for (int j = 0; j < 8; j++) {
            #pragma unroll
            for (int h2 = 0; h2 < 2; h2++) {
                int rr = m0 + wm * 32 + i * 16 + er + h2 * 8;
                int nb = n0 + wn * 64 + j * 8 + ec;
                #pragma unroll
                for (int t = 0; t < 2; t++) {
                    int n = nb + t;
                    float x = acc[i][j][h2 * 2 + t] + Bi[n];
                    if (!QKV) {
                        Outf[(size_t)rr * DM + n] = x;
                    } else {
                        bf hi, lo;
                        if (z == 0) {
                            x *= 0.125f;
                            bsplit(x, hi, lo);
                            qh[(size_t)rr * DM + n] = hi; ql[(size_t)rr * DM + n] = lo;
                        } else if (z == 1) {
                            bsplit(x, hi, lo);
                            kh[(size_t)rr * DM + n] = hi; kl[(size_t)rr * DM + n] = lo;
                        } else {
                            int hh = n >> 6, d = n & 63;
                            int zz = (rr >> 11) * NH + hh, s = rr & 2047;
                            size_t base = (size_t)zz * HD * SEQ + (size_t)d * SEQ + s;
                            bsplit(x, hi, lo);
                            vth[base] = hi; vtl[base] = lo;
                        }
                    }
                }
            }
        }
    }
}

// ---------------------------------------------------------------------------
// Fused flash attention (planar hi/lo). Block = 128 queries x 1 head.
// Q/K smem tiles: cols 0-63 hi, 64-127 lo. S = QhKh + QlKh + QhKl.
// PV = Ph·Vh + Pl·Vh + Ph·Vl. ctx written as hi/lo planes.
// ---------------------------------------------------------------------------
#define FA_QS    0
#define FA_KS    17408                    // Q: 128 x 136
#define FA_VS    34816                    // K: 2 buf x 64 x 136
#define FA_MSK_B 106496                   // after V: 2 buf x 2 planes x 64 x 72
#define FA_FLG_B 114688
#define FA_SMEM  114816

__global__ void __launch_bounds__(256, 1)
flash_attn(const bf* __restrict__ Qh, const bf* __restrict__ Ql,
           const bf* __restrict__ Kh, const bf* __restrict__ Kl,
           const bf* __restrict__ Vh, const bf* __restrict__ Vl,
           const int* __restrict__ mask,
           bf* __restrict__ Ch, bf* __restrict__ Cl)
{
    extern __shared__ __align__(16) bf sm[];
    bf* Qs = sm + FA_QS;
    bf* Ks = sm + FA_KS;
    bf* Vs = sm + FA_VS;
    int* msk = (int*)((char*)sm + FA_MSK_B);
    int* flg = (int*)((char*)sm + FA_FLG_B);

    const int tid = threadIdx.x, lane = tid & 31, w = tid >> 5;
    const int qb = blockIdx.x, z = blockIdx.y;
    const int b = z >> 4, h = z & 15;

    const bf* Qhp = Qh + ((size_t)(b * SEQ + qb * 128)) * DM + h * HD;
    const bf* Qlp = Ql + ((size_t)(b * SEQ + qb * 128)) * DM + h * HD;
    const bf* Khp = Kh + ((size_t)(b * SEQ)) * DM + h * HD;
    const bf* Klp = Kl + ((size_t)(b * SEQ)) * DM + h * HD;
    const bf* Vhp = Vh + (size_t)z * HD * SEQ;
    const bf* Vlp = Vl + (size_t)z * HD * SEQ;

    if (tid < 32) flg[tid] = 0;
    __syncthreads();
    #pragma unroll
    for (int i = 0; i < 8; i++) {
        int k = tid + i * 256;
        int m = mask[b * SEQ + k];
        msk[k] = m;
        if (m == 0) flg[k >> 6] = 1;
    }

    // Q tile: 128 rows x (64 hi | 64 lo)
    {
        int r = tid >> 1, q = tid & 1;
        #pragma unroll
        for (int i = 0; i < 4; i++) {
            int cc = (q + i * 2) * 8;
            CPASYNC(su32(Qs + r * 136 + cc),      Qhp + (size_t)r * DM + cc);
            CPASYNC(su32(Qs + r * 136 + 64 + cc), Qlp + (size_t)r * DM + cc);
        }
    }
    auto loadKV = [&](int kb, int st) {
        int r = tid >> 2, q = tid & 3;
        #pragma unroll
        for (int i = 0; i < 2; i++) {
            int cc = (q + i * 4) * 8;
            CPASYNC(su32(Ks + st * 8704 + r * 136 + cc),
                    Khp + (size_t)(kb * 64 + r) * DM + cc);
            CPASYNC(su32(Ks + st * 8704 + r * 136 + 64 + cc),
                    Klp + (size_t)(kb * 64 + r) * DM + cc);
            CPASYNC(su32(Vs + st * 9216 + r * 72 + cc),
                    Vhp + (size_t)r * SEQ + kb * 64 + cc);
            CPASYNC(su32(Vs + st * 9216 + 4608 + r * 72 + cc),
                    Vlp + (size_t)r * SEQ + kb * 64 + cc);
        }
    };
    loadKV(0, 0); CPCOMMIT();

    const int frow = ((lane >> 3) & 1) * 8 + (lane & 7);
    const int fcol = ((lane >> 4) & 1) * 8;
    const int er = lane >> 2, ec = (lane & 3) * 2;

    uint32_t qf[8][4];
    float Oa[8][4];
    #pragma unroll
    for (int j = 0; j < 8; j++)
        #pragma unroll
        for (int t = 0; t < 4; t++) Oa[j][t] = 0.f;
    float mrow[2] = { -1e30f, -1e30f }, lrow[2] = { 0.f, 0.f };

    for (int kb = 0; kb < 32; kb++) {
        const int st = kb & 1;
        if (kb + 1 < 32) { loadKV(kb + 1, st ^ 1); CPCOMMIT(); CPWAIT1(); }
        else             { CPWAIT0(); }
        __syncthreads();
        if (kb == 0) {
            #pragma unroll
            for (int k16 = 0; k16 < 8; k16++)
                ldm4(qf[k16], su32(Qs + (w * 16 + frow) * 136 + k16 * 16 + fcol));
        }

        // ---- S = QhKh + QlKh + QhKl (16 x 64 per warp) ----
        float Sa[8][4];
        #pragma unroll
        for (int j = 0; j < 8; j++)
            #pragma unroll
            for (int t = 0; t < 4; t++) Sa[j][t] = 0.f;

        const bf* kbuf = Ks + st * 8704;
        #pragma unroll
        for (int j = 0; j < 4; j++) {
            #pragma unroll
            for (int k = 0; k < 4; k++) {
                uint32_t bh4[4], bl4[4];
                ldm4(bh4, su32(kbuf + (j * 16 + frow) * 136 + k * 16 + fcol));
                ldm4(bl4, su32(kbuf + (j * 16 + frow) * 136 + (k + 4) * 16 + fcol));
                mma16816(Sa[2 * j],     qf[k],     bh4[0], bh4[2]);
                mma16816(Sa[2 * j + 1], qf[k],     bh4[1], bh4[3]);
                mma16816(Sa[2 * j],     qf[k + 4], bh4[0], bh4[2]);
                mma16816(Sa[2 * j + 1], qf[k + 4], bh4[1], bh4[3]);
                mma16816(Sa[2 * j],     qf[k],     bl4[0], bl4[2]);
                mma16816(Sa[2 * j + 1], qf[k],     bl4[1], bl4[3]);
            }
        }

        // ---- mask ----
        if (flg[kb]) {
            #pragma unroll
            for (int j = 0; j < 8; j++) {
                int c0 = kb * 64 + j * 8 + ec;
                if (!msk[c0])     { Sa[j][0] = -1e9f; Sa[j][2] = -1e9f; }
                if (!msk[c0 + 1]) { Sa[j][1] = -1e9f; Sa[j][3] = -1e9f; }
            }
        }

        // ---- online softmax (rows er, er+8) ----
        float mx0 = -1e30f, mx1 = -1e30f;
        #pragma unroll
        for (int j = 0; j < 8; j++) {
            mx0 = fmaxf(mx0, fmaxf(Sa[j][0], Sa[j][1]));
            mx1 = fmaxf(mx1, fmaxf(Sa[j][2], Sa[j][3]));
        }
        #pragma unroll
        for (int o = 1; o <= 2; o <<= 1) {
            mx0 = fmaxf(mx0, __shfl_xor_sync(0xffffffffu, mx0, o));
            mx1 = fmaxf(mx1, __shfl_xor_sync(0xffffffffu, mx1, o));
        }
        float nm0 = fmaxf(mrow[0], mx0), nm1 = fmaxf(mrow[1], mx1);
        float cor0 = __expf(mrow[0] - nm0), cor1 = __expf(mrow[1] - nm1);
        mrow[0] = nm0; mrow[1] = nm1;

        float rs0 = 0.f, rs1 = 0.f;
        #pragma unroll
        for (int j = 0; j < 8; j++) {
            Sa[j][0] = __expf(Sa[j][0] - nm0); rs0 += Sa[j][0];
            Sa[j][1] = __expf(Sa[j][1] - nm0); rs0 += Sa[j][1];
            Sa[j][2] = __expf(Sa[j][2] - nm1); rs1 += Sa[j][2];
            Sa[j][3] = __expf(Sa[j][3] - nm1); rs1 += Sa[j][3];
        }
        #pragma unroll
        for (int o = 1; o <= 2; o <<= 1) {
            rs0 += __shfl_xor_sync(0xffffffffu, rs0, o);
            rs1 += __shfl_xor_sync(0xffffffffu, rs1, o);
        }
        lrow[0] = lrow[0] * cor0 + rs0;
        lrow[1] = lrow[1] * cor1 + rs1;
        #pragma unroll
        for (int j = 0; j < 8; j++) {
            Oa[j][0] *= cor0; Oa[j][1] *= cor0;
            Oa[j][2] *= cor1; Oa[j][3] *= cor1;
        }

        // ---- PV: O += Ph·Vh + Pl·Vh + Ph·Vl ----
        const bf* vh = Vs + st * 9216;
        const bf* vl = vh + 4608;
        #pragma unroll
        for (int c = 0; c < 4; c++) {
            float a0 = Sa[2*c][0], a1 = Sa[2*c][1], a2 = Sa[2*c][2], a3 = Sa[2*c][3];
            float b0 = Sa[2*c+1][0], b1 = Sa[2*c+1][1], b2 = Sa[2*c+1][2], b3 = Sa[2*c+1][3];
            uint32_t ph[4], pl[4];
            ph[0] = pk2(a0, a1); ph[1] = pk2(a2, a3);
            ph[2] = pk2(b0, b1); ph[3] = pk2(b2, b3);
            pl[0] = pk2(a0 - bhi(a0), a1 - bhi(a1));
            pl[1] = pk2(a2 - bhi(a2), a3 - bhi(a3));
            pl[2] = pk2(b0 - bhi(b0), b1 - bhi(b1));
            pl[3] = pk2(b2 - bhi(b2), b3 - bhi(b3));
            #pragma unroll
            for (int t = 0; t < 4; t++) {
                uint32_t bh4[4], bl4[4];
                ldm4(bh4, su32(vh + (t * 16 + frow) * 72 + c * 16 + fcol));
                ldm4(bl4, su32(vl + (t * 16 + frow) * 72 + c * 16 + fcol));
                mma16816(Oa[2 * t],     ph, bh4[0], bh4[2]);
                mma16816(Oa[2 * t + 1], ph, bh4[1], bh4[3]);
                mma16816(Oa[2 * t],     pl, bh4[0], bh4[2]);
                mma16816(Oa[2 * t + 1], pl, bh4[1], bh4[3]);
                mma16816(Oa[2 * t],     ph, bl4[0], bl4[2]);
                mma16816(Oa[2 * t + 1], ph, bl4[1], bl4[3]);
            }
        }
        __syncthreads();
    }

    // ---- epilogue: normalize, write ctx hi/lo planes ----
    float i0 = 1.f / lrow[0], i1 = 1.f / lrow[1];
    int r0g = b * SEQ + qb * 128 + w * 16 + er;
    size_t base0 = (size_t)r0g * DM + h * HD;
    size_t base1 = base0 + (size_t)8 * DM;
    #pragma unroll
    for (int j = 0; j < 8; j++) {
        int d0 = j * 8 + ec;
        float v00 = Oa[j][0] * i0, v01 = Oa[j][1] * i0;
        float v10 = Oa[j][2] * i1, v11 = Oa[j][3] * i1;
        bf h00, l00, h01, l01, h10, l10, h11, l11;
        bsplit(v00, h00, l00); bsplit(v01, h01, l01);
        bsplit(v10, h10, l10); bsplit(v11, h11, l11);
        *(__nv_bfloat162*)(Ch + base0 + d0) = __nv_bfloat162(h00, h01);
        *(__nv_bfloat162*)(Cl + base0 + d0) = __nv_bfloat162(l00, l01);
        *(__nv_bfloat162*)(Ch + base1 + d0) = __nv_bfloat162(h10, h11);
        *(__nv_bfloat162*)(Cl + base1 + d0) = __nv_bfloat162(l10, l11);
    }
}

// ---------------------------------------------------------------------------
extern "C" void kernel_launch(void* const* d_in, const int* in_sizes, int n_in,
                              void* d_out, int out_size)
{
    const float* query = (const float*)d_in[0];
    const float* key   = (const float*)d_in[1];
    const float* value = (const float*)d_in[2];
    const int*   mask  = (const int*)d_in[3];
    const float* wq = (const float*)d_in[4];  const float* bq = (const float*)d_in[5];
    const float* wk = (const float*)d_in[6];  const float* bk = (const float*)d_in[7];
    const float* wv = (const float*)d_in[8];  const float* bv = (const float*)d_in[9];
    const float* wo = (const float*)d_in[10]; const float* bo = (const float*)d_in[11];

    #define SYM(p, sname) void* p; cudaGetSymbolAddress(&p, sname)
    SYM(xh, g_xh); SYM(xl, g_xl); SYM(wph, g_wph); SYM(wpl, g_wpl);
    SYM(qh, g_qh); SYM(ql, g_ql); SYM(kh, g_kh); SYM(kl, g_kl);
    SYM(vth, g_vth); SYM(vtl, g_vtl); SYM(ch, g_ch); SYM(cl, g_cl);
    #undef SYM

    const int GEMM_SMEM = 8 * GPL * (int)sizeof(bf);   // 81920
    static bool init = false;
    if (!init) {
        cudaFuncSetAttribute(flash_attn, cudaFuncAttributeMaxDynamicSharedMemorySize,
                             FA_SMEM);
        cudaFuncSetAttribute(gemm_bf<1>, cudaFuncAttributeMaxDynamicSharedMemorySize,
                             GEMM_SMEM);
        cudaFuncSetAttribute(gemm_bf<0>, cudaFuncAttributeMaxDynamicSharedMemorySize,
                             GEMM_SMEM);
        init = true;
    }

    // 1) one-time splits: inputs (3 x 4M) + weights (4 x 1M)
    const int N4 = NELEM / 4, W4 = WELEM / 4;
    split_pair<<<N4 / 256, 256>>>((const float4*)query, (uint2*)xh,
                                  (uint2*)xl, N4);
    split_pair<<<N4 / 256, 256>>>((const float4*)key, (uint2*)((bf*)xh + NELEM),
                                  (uint2*)((bf*)xl + NELEM), N4);
    split_pair<<<N4 / 256, 256>>>((const float4*)value, (uint2*)((bf*)xh + 2*NELEM),
                                  (uint2*)((bf*)xl + 2*NELEM), N4);
    split_pair<<<W4 / 256, 256>>>((const float4*)wq, (uint2*)wph, (uint2*)wpl, W4);
    split_pair<<<W4 / 256, 256>>>((const float4*)wk, (uint2*)((bf*)wph + WELEM),
                                  (uint2*)((bf*)wpl + WELEM), W4);
    split_pair<<<W4 / 256, 256>>>((const float4*)wv, (uint2*)((bf*)wph + 2*WELEM),
                                  (uint2*)((bf*)wpl + 2*WELEM), W4);
    split_pair<<<W4 / 256, 256>>>((const float4*)wo, (uint2*)((bf*)wph + 3*WELEM),
                                  (uint2*)((bf*)wpl + 3*WELEM), W4);

    // 2) Q/K/V projections (pure bf16 pipelined GEMM)
    gemm_bf<1><<<dim3(8, 32, 3), 256, GEMM_SMEM>>>(
        (bf*)xh, (bf*)xl, (bf*)wph, (bf*)wpl, bq, bk, bv,
        nullptr, (bf*)qh, (bf*)ql, (bf*)kh, (bf*)kl, (bf*)vth, (bf*)vtl);

    // 3) fused flash attention
    flash_attn<<<dim3(SEQ / 128, ZH), 256, FA_SMEM>>>(
        (bf*)qh, (bf*)ql, (bf*)kh, (bf*)kl, (bf*)vth, (bf*)vtl, mask,
        (bf*)ch, (bf*)cl);

    // 4) output projection
    gemm_bf<0><<<dim3(8, 32, 1), 256, GEMM_SMEM>>>(
        (bf*)ch, (bf*)cl, (bf*)wph + 3*WELEM, (bf*)wpl + 3*WELEM, bo, nullptr, nullptr,
        (float*)d_out, nullptr, nullptr, nullptr, nullptr, nullptr, nullptr);
}

// round 11
// speedup vs baseline: 1.4782x; 1.4417x over previous
#include <cuda_runtime.h>
#include <cuda_fp16.h>
#include <math.h>
#include <stdint.h>

#define SEQ   2048
#define DM    1024
#define NH    16
#define HD    64
#define MROWS 4096
#define ZH    32
#define NELEM (MROWS*DM)      // 4M
#define WELEM (DM*DM)         // 1M

// ---------------------------------------------------------------------------
// Scratch (__device__ globals; no allocations allowed)
// ---------------------------------------------------------------------------
__device__ __half g_xh[3*NELEM], g_xl[3*NELEM];   // split inputs (q,k,v), hi+lo
__device__ __half g_wh[4*WELEM];                  // weights hi only (B-side)
__device__ __half g_qh[NELEM], g_ql[NELEM];       // projected Q hi/lo (pre-scaled)
__device__ __half g_kh[NELEM];                    // projected K hi only
__device__ __half g_vth[ZH*HD*SEQ];               // projected V^T per head, hi only
__device__ __half g_ch[NELEM], g_cl[NELEM];       // context hi/lo

// ---------------------------------------------------------------------------
// PTX helpers
// ---------------------------------------------------------------------------
__device__ __forceinline__ uint32_t su32(const void* p) {
    uint32_t a;
    asm("{ .reg .u64 t; cvta.to.shared.u64 t, %1; cvt.u32.u64 %0, t; }" : "=r"(a) : "l"(p));
    return a;
}
#define CPASYNC(d, s) asm volatile("cp.async.cg.shared.global [%0], [%1], 16;" :: "r"(d), "l"(s))
#define CPCOMMIT()    asm volatile("cp.async.commit_group;")
#define CPWAIT0()     asm volatile("cp.async.wait_group 0;")
#define CPWAIT1()     asm volatile("cp.async.wait_group 1;")

__device__ __forceinline__ void ldm4(uint32_t* r, uint32_t addr) {
    asm volatile("ldmatrix.sync.aligned.m8n8.x4.shared.b16 {%0,%1,%2,%3}, [%4];"
                 : "=r"(r[0]), "=r"(r[1]), "=r"(r[2]), "=r"(r[3]) : "r"(addr));
}
__device__ __forceinline__ void mma16816(float* c, const uint32_t* a, uint32_t b0, uint32_t b1) {
    asm volatile("mma.sync.aligned.m16n8k16.row.col.f32.f16.f16.f32 "
                 "{%0,%1,%2,%3}, {%4,%5,%6,%7}, {%8,%9}, {%0,%1,%2,%3};"
                 : "+f"(c[0]), "+f"(c[1]), "+f"(c[2]), "+f"(c[3])
                 : "r"(a[0]), "r"(a[1]), "r"(a[2]), "r"(a[3]), "r"(b0), "r"(b1));
}
__device__ __forceinline__ float hhi(float x) {           // round-trip fp16
    return __half2float(__float2half_rn(x));
}
__device__ __forceinline__ uint32_t pk2h(float lo, float hi) {  // {lo@0-15, hi@16-31}
    uint32_t r;
    asm("cvt.rn.f16x2.f32 %0, %1, %2;" : "=r"(r) : "f"(hi), "f"(lo));
    return r;
}
__device__ __forceinline__ void hsplit(float x, __half& h, __half& l) {
    h = __float2half_rn(x);
    l = __float2half_rn(x - __half2float(h));
}

// ---------------------------------------------------------------------------
// fp32 -> fp16 hi/lo split (inputs, A-side), grid (n4blk, 3)
// ---------------------------------------------------------------------------
__global__ void __launch_bounds__(256)
split_in(const float4* __restrict__ q, const float4* __restrict__ k,
         const float4* __restrict__ v, uint2* __restrict__ hi,
         uint2* __restrict__ lo, int n4)
{
    int i = blockIdx.x * 256 + threadIdx.x;
    if (i >= n4) return;
    const float4* src = (blockIdx.y == 0) ? q : (blockIdx.y == 1) ? k : v;
    float4 x = src[i];
    float hx = hhi(x.x), hy = hhi(x.y), hz = hhi(x.z), hw = hhi(x.w);
    uint2 h, l;
    h.x = pk2h(x.x, x.y);           h.y = pk2h(x.z, x.w);
    l.x = pk2h(x.x - hx, x.y - hy); l.y = pk2h(x.z - hz, x.w - hw);
    size_t off = (size_t)blockIdx.y * (NELEM / 4);
    hi[off + i] = h; lo[off + i] = l;
}
// fp32 -> fp16 convert-only (weights, B-side), grid (n4blk, 4)
__global__ void __launch_bounds__(256)
conv_w(const float4* __restrict__ wq, const float4* __restrict__ wk,
       const float4* __restrict__ wv, const float4* __restrict__ wo,
       uint2* __restrict__ out, int n4)
{
    int i = blockIdx.x * 256 + threadIdx.x;
    if (i >= n4) return;
    const float4* src = (blockIdx.y == 0) ? wq : (blockIdx.y == 1) ? wk
                      : (blockIdx.y == 2) ? wv : wo;
    float4 x = src[i];
    uint2 h;
    h.x = pk2h(x.x, x.y); h.y = pk2h(x.z, x.w);
    out[(size_t)blockIdx.y * (WELEM / 4) + i] = h;
}

#define GPL 5120   // elements per smem plane buffer (128 x 40)

// ---------------------------------------------------------------------------
// fp16 2-term GEMM: C = (Ah+Al) @ Bh^T (+bias). 128x128 tile, BK=32,
// cp.async double-buffered, 2 CTAs/SM. 64 MMA / warp / K-tile.
// QKV=1: grid (8,32,3): z=0 Q (scaled, hi/lo), z=1 K (hi), z=2 V (hi, transposed)
// QKV=0: out-projection (fp32 out)
// ---------------------------------------------------------------------------
template<int QKV>
__global__ void __launch_bounds__(256, 2)
gemm_fp16(const __half* __restrict__ Xh, const __half* __restrict__ Xl,
          const __half* __restrict__ Wh,
          const float* __restrict__ bq, const float* __restrict__ bk,
          const float* __restrict__ bv,
          float* __restrict__ Outf,
          __half* __restrict__ qh, __half* __restrict__ ql,
          __half* __restrict__ kh, __half* __restrict__ vth)
{
    extern __shared__ __align__(16) __half gsm[];
    __half* AH = gsm;            // [2][128][40]
    __half* AL = gsm + 2 * GPL;
    __half* BH = gsm + 4 * GPL;

    const int tid = threadIdx.x, lane = tid & 31, wid = tid >> 5;
    const int m0 = blockIdx.y * 128, n0 = blockIdx.x * 128;
    const int z = QKV ? blockIdx.z : 0;

    const __half* Ahp = Xh + (QKV ? (size_t)z * NELEM : 0) + (size_t)m0 * DM;
    const __half* Alp = Xl + (QKV ? (size_t)z * NELEM : 0) + (size_t)m0 * DM;
    const __half* Bhp = Wh + (QKV ? (size_t)z * WELEM : 0) + (size_t)n0 * DM;
    const float* Bi = QKV ? ((z == 0) ? bq : (z == 1) ? bk : bv) : bq;

    auto loadTile = [&](int kt, int st) {
        const int kb = kt * 32;
        const int r = tid >> 1, c0 = (tid & 1) * 16;
        __half* ah = AH + st * GPL; __half* al = AL + st * GPL;
        __half* bh = BH + st * GPL;
        CPASYNC(su32(&ah[r * 40 + c0]),     Ahp + (size_t)r * DM + kb + c0);
        CPASYNC(su32(&ah[r * 40 + c0 + 8]), Ahp + (size_t)r * DM + kb + c0 + 8);
        CPASYNC(su32(&al[r * 40 + c0]),     Alp + (size_t)r * DM + kb + c0);
        CPASYNC(su32(&al[r * 40 + c0 + 8]), Alp + (size_t)r * DM + kb + c0 + 8);
        CPASYNC(su32(&bh[r * 40 + c0]),     Bhp + (size_t)r * DM + kb + c0);
        CPASYNC(su32(&bh[r * 40 + c0 + 8]), Bhp + (size_t)r * DM + kb + c0 + 8);
    };

    const int wm = wid >> 1, wn = wid & 1;
    float acc[2][8][4];
    #pragma unroll
    for (int i = 0; i < 2; i++)
        #pragma unroll
        for (int j = 0; j < 8; j++)
            #pragma unroll
            for (int t = 0; t < 4; t++) acc[i][j][t] = 0.f;

    const int frow = ((lane >> 3) & 1) * 8 + (lane & 7);
    const int fcol = ((lane >> 4) & 1) * 8;

    loadTile(0, 0); CPCOMMIT();

    for (int kt = 0; kt < 32; kt++) {
        const int st = kt & 1;
        if (kt < 31) { loadTile(kt + 1, st ^ 1); CPCOMMIT(); CPWAIT1(); }
        else         { CPWAIT0(); }
        __syncthreads();

        const __half* ah = AH + st * GPL; const __half* al = AL + st * GPL;
        const __half* bh = BH + st * GPL;
        #pragma unroll
        for (int k16 = 0; k16 < 2; k16++) {
            uint32_t a_h[2][4], a_l[2][4];
            #pragma unroll
            for (int i = 0; i < 2; i++) {
                ldm4(a_h[i], su32(&ah[(wm * 32 + i * 16 + frow) * 40 + k16 * 16 + fcol]));
                ldm4(a_l[i], su32(&al[(wm * 32 + i * 16 + frow) * 40 + k16 * 16 + fcol]));
            }
            #pragma unroll
            for (int j = 0; j < 4; j++) {
                uint32_t b_h[4];
                ldm4(b_h, su32(&bh[(wn * 64 + j * 16 + frow) * 40 + k16 * 16 + fcol]));
                #pragma unroll
                for (int i = 0; i < 2; i++) {
                    mma16816(acc[i][2 * j],     a_h[i], b_h[0], b_h[2]);
                    mma16816(acc[i][2 * j + 1], a_h[i], b_h[1], b_h[3]);
                    mma16816(acc[i][2 * j],     a_l[i], b_h[0], b_h[2]);
                    mma16816(acc[i][2 * j + 1], a_l[i], b_h[1], b_h[3]);
                }
            }
        }
        __syncthreads();
    }

    const int er = lane >> 2, ec = (lane & 3) * 2;
    #pragma unroll
    for (int i = 0; i < 2; i++) {
        #pragma unroll
        for (int j = 0; j < 8; j++) {
            #pragma unroll
            for (int h2 = 0; h2 < 2; h2++) {
                int rr = m0 + wm * 32 + i * 16 + er + h2 * 8;
                int nb = n0 + wn * 64 + j * 8 + ec;
                #pragma unroll
                for (int t = 0; t < 2; t++) {
                    int n = nb + t;
                    float x = acc[i][j][h2 * 2 + t] + Bi[n];
                    if (!QKV) {
                        Outf[(size_t)rr * DM + n] = x;
                    } else if (z == 0) {
                        x *= 0.125f;
                        __half h, l; hsplit(x, h, l);
                        qh[(size_t)rr * DM + n] = h; ql[(size_t)rr * DM + n] = l;
                    } else if (z == 1) {
                        kh[(size_t)rr * DM + n] = __float2half_rn(x);
                    } else {
                        int hd = n >> 6, d = n & 63;
                        int zz = (rr >> 11) * NH + hd, s = rr & 2047;
                        vth[(size_t)zz * HD * SEQ + (size_t)d * SEQ + s] = __float2half_rn(x);
                    }
                }
            }
        }
    }
}

// ---------------------------------------------------------------------------
// Fused flash attention, fp16 2-term. Block = 128 queries x 1 head, 2 CTAs/SM.
// S = (Qh+Ql)·Kh^T. PV = (Ph+Pl)·Vh. ctx written hi/lo.
// smem (halves): Q 128x136 | K 2x64x72 | V 2x64x72 | mask bitmap + flags
// ---------------------------------------------------------------------------
#define FA_QS    0
#define FA_KS    17408
#define FA_VS    26624
#define FA_MB_B  71680              // byte offset of bitmap (64 u32)
#define FA_FLG_B 71936              // byte offset of flags (32 ints)
#define FA_SMEM  72064

__global__ void __launch_bounds__(256, 2)
flash_attn(const __half* __restrict__ Qh, const __half* __restrict__ Ql,
           const __half* __restrict__ Kh, const __half* __restrict__ Vh,
           const int* __restrict__ mask,
           __half* __restrict__ Ch, __half* __restrict__ Cl)
{
    extern __shared__ __align__(16) __half sm[];
    __half* Qs = sm + FA_QS;
    __half* Ks = sm + FA_KS;
    __half* Vs = sm + FA_VS;
    uint32_t* mb = (uint32_t*)((char*)sm + FA_MB_B);
    int* flg = (int*)((char*)sm + FA_FLG_B);

    const int tid = threadIdx.x, lane = tid & 31, w = tid >> 5;
    const int qb = blockIdx.x, z = blockIdx.y;
    const int b = z >> 4, h = z & 15;

    const __half* Qhp = Qh + ((size_t)(b * SEQ + qb * 128)) * DM + h * HD;
    const __half* Qlp = Ql + ((size_t)(b * SEQ + qb * 128)) * DM + h * HD;
    const __half* Khp = Kh + ((size_t)(b * SEQ)) * DM + h * HD;
    const __half* Vhp = Vh + (size_t)z * HD * SEQ;

    if (tid < 32) flg[tid] = 0;
    __syncthreads();
    #pragma unroll
    for (int i = 0; i < 8; i++) {
        int k = i * 256 + tid;
        int m = mask[b * SEQ + k];
        uint32_t bits = __ballot_sync(0xffffffffu, m != 0);
        if (lane == 0) {
            mb[k >> 5] = bits;
            if (bits != 0xffffffffu) flg[k >> 6] = 1;
        }
    }

    // Q tile: 128 rows x (64 hi | 64 lo)
    {
        int r = tid >> 1, q = tid & 1;
        #pragma unroll
        for (int i = 0; i < 4; i++) {
            int cc = (q + i * 2) * 8;
            CPASYNC(su32(Qs + r * 136 + cc),      Qhp + (size_t)r * DM + cc);
            CPASYNC(su32(Qs + r * 136 + 64 + cc), Qlp + (size_t)r * DM + cc);
        }
    }
    auto loadKV = [&](int kb, int st) {
        int r = tid >> 2, q = tid & 3;
        #pragma unroll
        for (int i = 0; i < 2; i++) {
            int cc = (q + i * 4) * 8;
            CPASYNC(su32(Ks + st * 4608 + r * 72 + cc),
                    Khp + (size_t)(kb * 64 + r) * DM + cc);
            CPASYNC(su32(Vs + st * 4608 + r * 72 + cc),
                    Vhp + (size_t)r * SEQ + kb * 64 + cc);
        }
    };
    loadKV(0, 0); CPCOMMIT();

    const int frow = ((lane >> 3) & 1) * 8 + (lane & 7);
    const int fcol = ((lane >> 4) & 1) * 8;
    const int er = lane >> 2, ec = (lane & 3) * 2;

    float Oa[8][4];
    #pragma unroll
    for (int j = 0; j < 8; j++)
        #pragma unroll
        for (int t = 0; t < 4; t++) Oa[j][t] = 0.f;
    float mrow[2] = { -1e30f, -1e30f }, lrow[2] = { 0.f, 0.f };

    for (int kb = 0; kb < 32; kb++) {
        const int st = kb & 1;
        if (kb + 1 < 32) { loadKV(kb + 1, st ^ 1); CPCOMMIT(); CPWAIT1(); }
        else             { CPWAIT0(); }
        __syncthreads();

        // ---- S = Qh·Kh + Ql·Kh (16 x 64 per warp) ----
        float Sa[8][4];
        #pragma unroll
        for (int j = 0; j < 8; j++)
            #pragma unroll
            for (int t = 0; t < 4; t++) Sa[j][t] = 0.f;

        const __half* kbuf = Ks + st * 4608;
        #pragma unroll
        for (int k = 0; k < 4; k++) {
            uint32_t qhf[4], qlf[4];
            ldm4(qhf, su32(Qs + (w * 16 + frow) * 136 + k * 16 + fcol));
            ldm4(qlf, su32(Qs + (w * 16 + frow) * 136 + 64 + k * 16 + fcol));
            #pragma unroll
            for (int j = 0; j < 4; j++) {
                uint32_t b4[4];
                ldm4(b4, su32(kbuf + (j * 16 + frow) * 72 + k * 16 + fcol));
                mma16816(Sa[2 * j],     qhf, b4[0], b4[2]);
                mma16816(Sa[2 * j + 1], qhf, b4[1], b4[3]);
                mma16816(Sa[2 * j],     qlf, b4[0], b4[2]);
                mma16816(Sa[2 * j + 1], qlf, b4[1], b4[3]);
            }
        }

        // ---- mask (bitmap) ----
        if (flg[kb]) {
            #pragma unroll
            for (int j = 0; j < 8; j++) {
                int c0 = kb * 64 + j * 8 + ec;
                if (!((mb[c0 >> 5] >> (c0 & 31)) & 1u))         { Sa[j][0] = -1e9f; Sa[j][2] = -1e9f; }
                if (!((mb[(c0+1) >> 5] >> ((c0+1) & 31)) & 1u)) { Sa[j][1] = -1e9f; Sa[j][3] = -1e9f; }
            }
        }

        // ---- online softmax (rows er, er+8) ----
        float mx0 = -1e30f, mx1 = -1e30f;
        #pragma unroll
        for (int j = 0; j < 8; j++) {
            mx0 = fmaxf(mx0, fmaxf(Sa[j][0], Sa[j][1]));
            mx1 = fmaxf(mx1, fmaxf(Sa[j][2], Sa[j][3]));
        }
        #pragma unroll
        for (int o = 1; o <= 2; o <<= 1) {
            mx0 = fmaxf(mx0, __shfl_xor_sync(0xffffffffu, mx0, o));
            mx1 = fmaxf(mx1, __shfl_xor_sync(0xffffffffu, mx1, o));
        }
        float nm0 = fmaxf(mrow[0], mx0), nm1 = fmaxf(mrow[1], mx1);
        float cor0 = __expf(mrow[0] - nm0), cor1 = __expf(mrow[1] - nm1);
        mrow[0] = nm0; mrow[1] = nm1;

        float rs0 = 0.f, rs1 = 0.f;
        #pragma unroll
        for (int j = 0; j < 8; j++) {
            Sa[j][0] = __expf(Sa[j][0] - nm0); rs0 += Sa[j][0];
            Sa[j][1] = __expf(Sa[j][1] - nm0); rs0 += Sa[j][1];
            Sa[j][2] = __expf(Sa[j][2] - nm1); rs1 += Sa[j][2];
            Sa[j][3] = __expf(Sa[j][3] - nm1); rs1 += Sa[j][3];
        }
        #pragma unroll
        for (int o = 1; o <= 2; o <<= 1) {
            rs0 += __shfl_xor_sync(0xffffffffu, rs0, o);
            rs1 += __shfl_xor_sync(0xffffffffu, rs1, o);
        }
        lrow[0] = lrow[0] * cor0 + rs0;
        lrow[1] = lrow[1] * cor1 + rs1;
        #pragma unroll
        for (int j = 0; j < 8; j++) {
            Oa[j][0] *= cor0; Oa[j][1] *= cor0;
            Oa[j][2] *= cor1; Oa[j][3] *= cor1;
        }

        // ---- PV: O += (Ph + Pl)·Vh ----
        const __half* vbuf = Vs + st * 4608;
        #pragma unroll
        for (int c = 0; c < 4; c++) {
            float a0 = Sa[2*c][0], a1 = Sa[2*c][1], a2 = Sa[2*c][2], a3 = Sa[2*c][3];
            float b0 = Sa[2*c+1][0], b1 = Sa[2*c+1][1], b2 = Sa[2*c+1][2], b3 = Sa[2*c+1][3];
            uint32_t ph[4], pl[4];
            ph[0] = pk2h(a0, a1); ph[1] = pk2h(a2, a3);
            ph[2] = pk2h(b0, b1); ph[3] = pk2h(b2, b3);
            pl[0] = pk2h(a0 - hhi(a0), a1 - hhi(a1));
            pl[1] = pk2h(a2 - hhi(a2), a3 - hhi(a3));
            pl[2] = pk2h(b0 - hhi(b0), b1 - hhi(b1));
            pl[3] = pk2h(b2 - hhi(b2), b3 - hhi(b3));
            #pragma unroll
            for (int t = 0; t < 4; t++) {
                uint32_t v4[4];
                ldm4(v4, su32(vbuf + (t * 16 + frow) * 72 + c * 16 + fcol));
                mma16816(Oa[2 * t],     ph, v4[0], v4[2]);
                mma16816(Oa[2 * t + 1], ph, v4[1], v4[3]);
                mma16816(Oa[2 * t],     pl, v4[0], v4[2]);
                mma16816(Oa[2 * t + 1], pl, v4[1], v4[3]);
            }
        }
        __syncthreads();
    }

    // ---- epilogue: normalize, write ctx hi/lo ----
    float i0 = 1.f / lrow[0], i1 = 1.f / lrow[1];
    int r0g = b * SEQ + qb * 128 + w * 16 + er;
    size_t base0 = (size_t)r0g * DM + h * HD;
    size_t base1 = base0 + (size_t)8 * DM;
    #pragma unroll
    for (int j = 0; j < 8; j++) {
        int d0 = j * 8 + ec;
        float v00 = Oa[j][0] * i0, v01 = Oa[j][1] * i0;
        float v10 = Oa[j][2] * i1, v11 = Oa[j][3] * i1;
        __half h00, l00, h01, l01, h10, l10, h11, l11;
        hsplit(v00, h00, l00); hsplit(v01, h01, l01);
        hsplit(v10, h10, l10); hsplit(v11, h11, l11);
        *(__half2*)(Ch + base0 + d0) = __halves2half2(h00, h01);
        *(__half2*)(Cl + base0 + d0) = __halves2half2(l00, l01);
        *(__half2*)(Ch + base1 + d0) = __halves2half2(h10, h11);
        *(__half2*)(Cl + base1 + d0) = __halves2half2(l10, l11);
    }
}

// ---------------------------------------------------------------------------
extern "C" void kernel_launch(void* const* d_in, const int* in_sizes, int n_in,
                              void* d_out, int out_size)
{
    const float* query = (const float*)d_in[0];
    const float* key   = (const float*)d_in[1];
    const float* value = (const float*)d_in[2];
    const int*   mask  = (const int*)d_in[3];
    const float* wq = (const float*)d_in[4];  const float* bq = (const float*)d_in[5];
    const float* wk = (const float*)d_in[6];  const float* bk = (const float*)d_in[7];
    const float* wv = (const float*)d_in[8];  const float* bv = (const float*)d_in[9];
    const float* wo = (const float*)d_in[10]; const float* bo = (const float*)d_in[11];

    #define SYM(p, sname) void* p; cudaGetSymbolAddress(&p, sname)
    SYM(xh, g_xh); SYM(xl, g_xl); SYM(wh, g_wh);
    SYM(qh, g_qh); SYM(ql, g_ql); SYM(kh, g_kh); SYM(vth, g_vth);
    SYM(ch, g_ch); SYM(cl, g_cl);
    #undef SYM
    typedef __half hf;

    const int GEMM_SMEM = 6 * GPL * (int)sizeof(hf);   // 61440
    static bool init = false;
    if (!init) {
        cudaFuncSetAttribute(flash_attn, cudaFuncAttributeMaxDynamicSharedMemorySize,
                             FA_SMEM);
        cudaFuncSetAttribute(gemm_fp16<1>, cudaFuncAttributeMaxDynamicSharedMemorySize,
                             GEMM_SMEM);
        cudaFuncSetAttribute(gemm_fp16<0>, cudaFuncAttributeMaxDynamicSharedMemorySize,
                             GEMM_SMEM);
        init = true;
    }

    // 1) splits: inputs hi/lo, weights hi-only
    split_in<<<dim3(NELEM / 4 / 256, 3), 256>>>(
        (const float4*)query, (const float4*)key, (const float4*)value,
        (uint2*)xh, (uint2*)xl, NELEM / 4);
    conv_w<<<dim3(WELEM / 4 / 256, 4), 256>>>(
        (const float4*)wq, (const float4*)wk, (const float4*)wv, (const float4*)wo,
        (uint2*)wh, WELEM / 4);

    // 2) Q/K/V projections
    gemm_fp16<1><<<dim3(8, 32, 3), 256, GEMM_SMEM>>>(
        (hf*)xh, (hf*)xl, (hf*)wh, bq, bk, bv,
        nullptr, (hf*)qh, (hf*)ql, (hf*)kh, (hf*)vth);

    // 3) fused flash attention
    flash_attn<<<dim3(SEQ / 128, ZH), 256, FA_SMEM>>>(
        (hf*)qh, (hf*)ql, (hf*)kh, (hf*)vth, mask, (hf*)ch, (hf*)cl);

    // 4) output projection
    gemm_fp16<0><<<dim3(8, 32, 1), 256, GEMM_SMEM>>>(
        (hf*)ch, (hf*)cl, (hf*)wh + 3 * (size_t)WELEM, bo, nullptr, nullptr,
        (float*)d_out, nullptr, nullptr, nullptr, nullptr);
}

// round 12
// speedup vs baseline: 1.6302x; 1.1029x over previous
#include <cuda_runtime.h>
#include <cuda_fp16.h>
#include <math.h>
#include <stdint.h>

#define SEQ   2048
#define DM    1024
#define NH    16
#define HD    64
#define MROWS 4096
#define ZH    32
#define NELEM (MROWS*DM)      // 4M
#define WELEM (DM*DM)         // 1M

// ---------------------------------------------------------------------------
// Scratch (__device__ globals; no allocations allowed)
// ---------------------------------------------------------------------------
__device__ __half g_xh[3*NELEM], g_xl[3*NELEM];   // split inputs (q,k,v), hi+lo
__device__ __half g_wh[4*WELEM];                  // weights hi only (B-side)
__device__ __half g_qh[NELEM], g_ql[NELEM];       // projected Q hi/lo (pre-scaled)
__device__ __half g_kh[NELEM];                    // projected K hi only
__device__ __half g_vth[ZH*HD*SEQ];               // projected V^T per head, hi only
__device__ __half g_ch[NELEM], g_cl[NELEM];       // context hi/lo

// ---------------------------------------------------------------------------
// PTX helpers
// ---------------------------------------------------------------------------
__device__ __forceinline__ uint32_t su32(const void* p) {
    uint32_t a;
    asm("{ .reg .u64 t; cvta.to.shared.u64 t, %1; cvt.u32.u64 %0, t; }" : "=r"(a) : "l"(p));
    return a;
}
#define CPASYNC(d, s) asm volatile("cp.async.cg.shared.global [%0], [%1], 16;" :: "r"(d), "l"(s))
#define CPCOMMIT()    asm volatile("cp.async.commit_group;")
#define CPWAIT0()     asm volatile("cp.async.wait_group 0;")
#define CPWAIT1()     asm volatile("cp.async.wait_group 1;")
#define CPWAIT2()     asm volatile("cp.async.wait_group 2;")

__device__ __forceinline__ void ldm4(uint32_t* r, uint32_t addr) {
    asm volatile("ldmatrix.sync.aligned.m8n8.x4.shared.b16 {%0,%1,%2,%3}, [%4];"
                 : "=r"(r[0]), "=r"(r[1]), "=r"(r[2]), "=r"(r[3]) : "r"(addr));
}
__device__ __forceinline__ void mma16816(float* c, const uint32_t* a, uint32_t b0, uint32_t b1) {
    asm volatile("mma.sync.aligned.m16n8k16.row.col.f32.f16.f16.f32 "
                 "{%0,%1,%2,%3}, {%4,%5,%6,%7}, {%8,%9}, {%0,%1,%2,%3};"
                 : "+f"(c[0]), "+f"(c[1]), "+f"(c[2]), "+f"(c[3])
                 : "r"(a[0]), "r"(a[1]), "r"(a[2]), "r"(a[3]), "r"(b0), "r"(b1));
}
__device__ __forceinline__ float hhi(float x) {           // round-trip fp16
    return __half2float(__float2half_rn(x));
}
__device__ __forceinline__ uint32_t pk2h(float lo, float hi) {  // {lo@0-15, hi@16-31}
    uint32_t r;
    asm("cvt.rn.f16x2.f32 %0, %1, %2;" : "=r"(r) : "f"(hi), "f"(lo));
    return r;
}
__device__ __forceinline__ void hsplit(float x, __half& h, __half& l) {
    h = __float2half_rn(x);
    l = __float2half_rn(x - __half2float(h));
}

// ---------------------------------------------------------------------------
// fp32 -> fp16 hi/lo split (inputs, A-side), grid (n4blk, 3)
// ---------------------------------------------------------------------------
__global__ void __launch_bounds__(256)
split_in(const float4* __restrict__ q, const float4* __restrict__ k,
         const float4* __restrict__ v, uint2* __restrict__ hi,
         uint2* __restrict__ lo, int n4)
{
    int i = blockIdx.x * 256 + threadIdx.x;
    if (i >= n4) return;
    const float4* src = (blockIdx.y == 0) ? q : (blockIdx.y == 1) ? k : v;
    float4 x = src[i];
    float hx = hhi(x.x), hy = hhi(x.y), hz = hhi(x.z), hw = hhi(x.w);
    uint2 h, l;
    h.x = pk2h(x.x, x.y);           h.y = pk2h(x.z, x.w);
    l.x = pk2h(x.x - hx, x.y - hy); l.y = pk2h(x.z - hz, x.w - hw);
    size_t off = (size_t)blockIdx.y * (NELEM / 4);
    hi[off + i] = h; lo[off + i] = l;
}
// fp32 -> fp16 convert-only (weights, B-side), grid (n4blk, 4)
__global__ void __launch_bounds__(256)
conv_w(const float4* __restrict__ wq, const float4* __restrict__ wk,
       const float4* __restrict__ wv, const float4* __restrict__ wo,
       uint2* __restrict__ out, int n4)
{
    int i = blockIdx.x * 256 + threadIdx.x;
    if (i >= n4) return;
    const float4* src = (blockIdx.y == 0) ? wq : (blockIdx.y == 1) ? wk
                      : (blockIdx.y == 2) ? wv : wo;
    float4 x = src[i];
    uint2 h;
    h.x = pk2h(x.x, x.y); h.y = pk2h(x.z, x.w);
    out[(size_t)blockIdx.y * (WELEM / 4) + i] = h;
}

#define GPL  5120    // halves per plane (128 x 40)
#define GSTG 15360   // halves per pipeline stage (ah + al + bh)

// ---------------------------------------------------------------------------
// fp16 2-term GEMM: C = (Ah+Al) @ Bh^T (+bias). 128x128 tile, BK=32,
// cp.async TRIPLE-buffered, 2 CTAs/SM.
// QKV=1: grid (8,32,3): z=0 Q (scaled, hi/lo), z=1 K (hi), z=2 V (hi, transposed)
// QKV=0: out-projection (fp32 out)
// ---------------------------------------------------------------------------
template<int QKV>
__global__ void __launch_bounds__(256, 2)
gemm_fp16(const __half* __restrict__ Xh, const __half* __restrict__ Xl,
          const __half* __restrict__ Wh,
          const float* __restrict__ bq, const float* __restrict__ bk,
          const float* __restrict__ bv,
          float* __restrict__ Outf,
          __half* __restrict__ qh, __half* __restrict__ ql,
          __half* __restrict__ kh, __half* __restrict__ vth)
{
    extern __shared__ __align__(16) __half gsm[];

    const int tid = threadIdx.x, lane = tid & 31, wid = tid >> 5;
    const int m0 = blockIdx.y * 128, n0 = blockIdx.x * 128;
    const int z = QKV ? blockIdx.z : 0;

    const __half* Ahp = Xh + (QKV ? (size_t)z * NELEM : 0) + (size_t)m0 * DM;
    const __half* Alp = Xl + (QKV ? (size_t)z * NELEM : 0) + (size_t)m0 * DM;
    const __half* Bhp = Wh + (QKV ? (size_t)z * WELEM : 0) + (size_t)n0 * DM;
    const float* Bi = QKV ? ((z == 0) ? bq : (z == 1) ? bk : bv) : bq;

    auto loadTile = [&](int kt, int st) {
        const int kb = kt * 32;
        const int r = tid >> 1, c0 = (tid & 1) * 16;
        __half* ah = gsm + st * GSTG;
        __half* al = ah + GPL;
        __half* bh = al + GPL;
        CPASYNC(su32(&ah[r * 40 + c0]),     Ahp + (size_t)r * DM + kb + c0);
        CPASYNC(su32(&ah[r * 40 + c0 + 8]), Ahp + (size_t)r * DM + kb + c0 + 8);
        CPASYNC(su32(&al[r * 40 + c0]),     Alp + (size_t)r * DM + kb + c0);
        CPASYNC(su32(&al[r * 40 + c0 + 8]), Alp + (size_t)r * DM + kb + c0 + 8);
        CPASYNC(su32(&bh[r * 40 + c0]),     Bhp + (size_t)r * DM + kb + c0);
        CPASYNC(su32(&bh[r * 40 + c0 + 8]), Bhp + (size_t)r * DM + kb + c0 + 8);
    };

    const int wm = wid >> 1, wn = wid & 1;
    float acc[2][8][4];
    #pragma unroll
    for (int i = 0; i < 2; i++)
        #pragma unroll
        for (int j = 0; j < 8; j++)
            #pragma unroll
            for (int t = 0; t < 4; t++) acc[i][j][t] = 0.f;

    const int frow = ((lane >> 3) & 1) * 8 + (lane & 7);
    const int fcol = ((lane >> 4) & 1) * 8;

    loadTile(0, 0); CPCOMMIT();
    loadTile(1, 1); CPCOMMIT();

    int st = 0;
    for (int kt = 0; kt < 32; kt++) {
        if (kt + 2 < 32) {
            int stl = st + 2; if (stl >= 3) stl -= 3;
            loadTile(kt + 2, stl); CPCOMMIT(); CPWAIT2();
        } else if (kt + 1 < 32) {
            CPWAIT1();
        } else {
            CPWAIT0();
        }
        __syncthreads();

        const __half* ah = gsm + st * GSTG;
        const __half* al = ah + GPL;
        const __half* bh = al + GPL;
        #pragma unroll
        for (int k16 = 0; k16 < 2; k16++) {
            uint32_t a_h[2][4], a_l[2][4];
            #pragma unroll
            for (int i = 0; i < 2; i++) {
                ldm4(a_h[i], su32(&ah[(wm * 32 + i * 16 + frow) * 40 + k16 * 16 + fcol]));
                ldm4(a_l[i], su32(&al[(wm * 32 + i * 16 + frow) * 40 + k16 * 16 + fcol]));
            }
            #pragma unroll
            for (int j = 0; j < 4; j++) {
                uint32_t b_h[4];
                ldm4(b_h, su32(&bh[(wn * 64 + j * 16 + frow) * 40 + k16 * 16 + fcol]));
                #pragma unroll
                for (int i = 0; i < 2; i++) {
                    mma16816(acc[i][2 * j],     a_h[i], b_h[0], b_h[2]);
                    mma16816(acc[i][2 * j + 1], a_h[i], b_h[1], b_h[3]);
                    mma16816(acc[i][2 * j],     a_l[i], b_h[0], b_h[2]);
                    mma16816(acc[i][2 * j + 1], a_l[i], b_h[1], b_h[3]);
                }
            }
        }
        __syncthreads();
        if (++st >= 3) st = 0;
    }

    const int er = lane >> 2, ec = (lane & 3) * 2;
    #pragma unroll
    for (int i = 0; i < 2; i++) {
        #pragma unroll
        for (int j = 0; j < 8; j++) {
            #pragma unroll
            for (int h2 = 0; h2 < 2; h2++) {
                int rr = m0 + wm * 32 + i * 16 + er + h2 * 8;
                int nb = n0 + wn * 64 + j * 8 + ec;
                #pragma unroll
                for (int t = 0; t < 2; t++) {
                    int n = nb + t;
                    float x = acc[i][j][h2 * 2 + t] + Bi[n];
                    if (!QKV) {
                        Outf[(size_t)rr * DM + n] = x;
                    } else if (z == 0) {
                        x *= 0.125f;
                        __half h, l; hsplit(x, h, l);
                        qh[(size_t)rr * DM + n] = h; ql[(size_t)rr * DM + n] = l;
                    } else if (z == 1) {
                        kh[(size_t)rr * DM + n] = __float2half_rn(x);
                    } else {
                        int hd = n >> 6, d = n & 63;
                        int zz = (rr >> 11) * NH + hd, s = rr & 2047;
                        vth[(size_t)zz * HD * SEQ + (size_t)d * SEQ + s] = __float2half_rn(x);
                    }
                }
            }
        }
    }
}

// ---------------------------------------------------------------------------
// Fused flash attention. Block = 128 queries x 1 head, 2 CTAs/SM.
// S = (Qh+Ql)·Kh^T (2-term). PV = Ph·Vh (1-term). K/V triple-buffered.
// l-sum computed AFTER PV so shuffle latency hides under MMAs.
// ---------------------------------------------------------------------------
#define FA_QS    0                        // Q: 128 x 136 halves
#define FA_KS    17408                    // K: 3 x 64 x 72
#define FA_VS    31232                    // V: 3 x 64 x 72
#define FA_MB_B  90112                    // bitmap: 64 u32
#define FA_FLG_B 90368                    // flags: 32 int
#define FA_SMEM  90496

__global__ void __launch_bounds__(256, 2)
flash_attn(const __half* __restrict__ Qh, const __half* __restrict__ Ql,
           const __half* __restrict__ Kh, const __half* __restrict__ Vh,
           const int* __restrict__ mask,
           __half* __restrict__ Ch, __half* __restrict__ Cl)
{
    extern __shared__ __align__(16) __half sm[];
    __half* Qs = sm + FA_QS;
    __half* Ks = sm + FA_KS;
    __half* Vs = sm + FA_VS;
    uint32_t* mb = (uint32_t*)((char*)sm + FA_MB_B);
    int* flg = (int*)((char*)sm + FA_FLG_B);

    const int tid = threadIdx.x, lane = tid & 31, w = tid >> 5;
    const int qb = blockIdx.x, z = blockIdx.y;
    const int b = z >> 4, h = z & 15;

    const __half* Qhp = Qh + ((size_t)(b * SEQ + qb * 128)) * DM + h * HD;
    const __half* Qlp = Ql + ((size_t)(b * SEQ + qb * 128)) * DM + h * HD;
    const __half* Khp = Kh + ((size_t)(b * SEQ)) * DM + h * HD;
    const __half* Vhp = Vh + (size_t)z * HD * SEQ;

    if (tid < 32) flg[tid] = 0;
    __syncthreads();
    #pragma unroll
    for (int i = 0; i < 8; i++) {
        int k = i * 256 + tid;
        int m = mask[b * SEQ + k];
        uint32_t bits = __ballot_sync(0xffffffffu, m != 0);
        if (lane == 0) {
            mb[k >> 5] = bits;
            if (bits != 0xffffffffu) flg[k >> 6] = 1;
        }
    }

    // Q tile: 128 rows x (64 hi | 64 lo)
    {
        int r = tid >> 1, q = tid & 1;
        #pragma unroll
        for (int i = 0; i < 4; i++) {
            int cc = (q + i * 2) * 8;
            CPASYNC(su32(Qs + r * 136 + cc),      Qhp + (size_t)r * DM + cc);
            CPASYNC(su32(Qs + r * 136 + 64 + cc), Qlp + (size_t)r * DM + cc);
        }
    }
    auto loadKV = [&](int kb, int st) {
        int r = tid >> 2, q = tid & 3;
        #pragma unroll
        for (int i = 0; i < 2; i++) {
            int cc = (q + i * 4) * 8;
            CPASYNC(su32(Ks + st * 4608 + r * 72 + cc),
                    Khp + (size_t)(kb * 64 + r) * DM + cc);
            CPASYNC(su32(Vs + st * 4608 + r * 72 + cc),
                    Vhp + (size_t)r * SEQ + kb * 64 + cc);
        }
    };
    loadKV(0, 0); CPCOMMIT();
    loadKV(1, 1); CPCOMMIT();

    const int frow = ((lane >> 3) & 1) * 8 + (lane & 7);
    const int fcol = ((lane >> 4) & 1) * 8;
    const int er = lane >> 2, ec = (lane & 3) * 2;

    float Oa[8][4];
    #pragma unroll
    for (int j = 0; j < 8; j++)
        #pragma unroll
        for (int t = 0; t < 4; t++) Oa[j][t] = 0.f;
    float mrow[2] = { -1e30f, -1e30f }, lrow[2] = { 0.f, 0.f };

    int st = 0;
    for (int kb = 0; kb < 32; kb++) {
        if (kb + 2 < 32) {
            int stl = st + 2; if (stl >= 3) stl -= 3;
            loadKV(kb + 2, stl); CPCOMMIT(); CPWAIT2();
        } else if (kb + 1 < 32) {
            CPWAIT1();
        } else {
            CPWAIT0();
        }
        __syncthreads();

        // ---- S = Qh·Kh + Ql·Kh (16 x 64 per warp) ----
        float Sa[8][4];
        #pragma unroll
        for (int j = 0; j < 8; j++)
            #pragma unroll
            for (int t = 0; t < 4; t++) Sa[j][t] = 0.f;

        const __half* kbuf = Ks + st * 4608;
        #pragma unroll
        for (int k = 0; k < 4; k++) {
            uint32_t qhf[4], qlf[4];
            ldm4(qhf, su32(Qs + (w * 16 + frow) * 136 + k * 16 + fcol));
            ldm4(qlf, su32(Qs + (w * 16 + frow) * 136 + 64 + k * 16 + fcol));
            #pragma unroll
            for (int j = 0; j < 4; j++) {
                uint32_t b4[4];
                ldm4(b4, su32(kbuf + (j * 16 + frow) * 72 + k * 16 + fcol));
                mma16816(Sa[2 * j],     qhf, b4[0], b4[2]);
                mma16816(Sa[2 * j + 1], qhf, b4[1], b4[3]);
                mma16816(Sa[2 * j],     qlf, b4[0], b4[2]);
                mma16816(Sa[2 * j + 1], qlf, b4[1], b4[3]);
            }
        }

        // ---- mask (bitmap) ----
        if (flg[kb]) {
            #pragma unroll
            for (int j = 0; j < 8; j++) {
                int c0 = kb * 64 + j * 8 + ec;
                if (!((mb[c0 >> 5] >> (c0 & 31)) & 1u))         { Sa[j][0] = -1e9f; Sa[j][2] = -1e9f; }
                if (!((mb[(c0+1) >> 5] >> ((c0+1) & 31)) & 1u)) { Sa[j][1] = -1e9f; Sa[j][3] = -1e9f; }
            }
        }

        // ---- online softmax: max + exp (rows er, er+8) ----
        float mx0 = -1e30f, mx1 = -1e30f;
        #pragma unroll
        for (int j = 0; j < 8; j++) {
            mx0 = fmaxf(mx0, fmaxf(Sa[j][0], Sa[j][1]));
            mx1 = fmaxf(mx1, fmaxf(Sa[j][2], Sa[j][3]));
        }
        #pragma unroll
        for (int o = 1; o <= 2; o <<= 1) {
            mx0 = fmaxf(mx0, __shfl_xor_sync(0xffffffffu, mx0, o));
            mx1 = fmaxf(mx1, __shfl_xor_sync(0xffffffffu, mx1, o));
        }
        float nm0 = fmaxf(mrow[0], mx0), nm1 = fmaxf(mrow[1], mx1);
        float cor0 = __expf(mrow[0] - nm0), cor1 = __expf(mrow[1] - nm1);
        mrow[0] = nm0; mrow[1] = nm1;

        #pragma unroll
        for (int j = 0; j < 8; j++) {
            Sa[j][0] = __expf(Sa[j][0] - nm0);
            Sa[j][1] = __expf(Sa[j][1] - nm0);
            Sa[j][2] = __expf(Sa[j][2] - nm1);
            Sa[j][3] = __expf(Sa[j][3] - nm1);
        }

        // ---- rescale O ----
        #pragma unroll
        for (int j = 0; j < 8; j++) {
            Oa[j][0] *= cor0; Oa[j][1] *= cor0;
            Oa[j][2] *= cor1; Oa[j][3] *= cor1;
        }

        // ---- PV: O += Ph·Vh (1-term) ----
        const __half* vbuf = Vs + st * 4608;
        #pragma unroll
        for (int c = 0; c < 4; c++) {
            uint32_t ph[4];
            ph[0] = pk2h(Sa[2*c][0],   Sa[2*c][1]);
            ph[1] = pk2h(Sa[2*c][2],   Sa[2*c][3]);
            ph[2] = pk2h(Sa[2*c+1][0], Sa[2*c+1][1]);
            ph[3] = pk2h(Sa[2*c+1][2], Sa[2*c+1][3]);
            #pragma unroll
            for (int t = 0; t < 4; t++) {
                uint32_t v4[4];
                ldm4(v4, su32(vbuf + (t * 16 + frow) * 72 + c * 16 + fcol));
                mma16816(Oa[2 * t],     ph, v4[0], v4[2]);
                mma16816(Oa[2 * t + 1], ph, v4[1], v4[3]);
            }
        }

        // ---- l-sum AFTER PV (shuffles overlap MMA latency) ----
        float rs0 = 0.f, rs1 = 0.f;
        #pragma unroll
        for (int j = 0; j < 8; j++) {
            rs0 += Sa[j][0] + Sa[j][1];
            rs1 += Sa[j][2] + Sa[j][3];
        }
        #pragma unroll
        for (int o = 1; o <= 2; o <<= 1) {
            rs0 += __shfl_xor_sync(0xffffffffu, rs0, o);
            rs1 += __shfl_xor_sync(0xffffffffu, rs1, o);
        }
        lrow[0] = lrow[0] * cor0 + rs0;
        lrow[1] = lrow[1] * cor1 + rs1;

        __syncthreads();
        if (++st >= 3) st = 0;
    }

    // ---- epilogue: normalize, write ctx hi/lo ----
    float i0 = 1.f / lrow[0], i1 = 1.f / lrow[1];
    int r0g = b * SEQ + qb * 128 + w * 16 + er;
    size_t base0 = (size_t)r0g * DM + h * HD;
    size_t base1 = base0 + (size_t)8 * DM;
    #pragma unroll
    for (int j = 0; j < 8; j++) {
        int d0 = j * 8 + ec;
        float v00 = Oa[j][0] * i0, v01 = Oa[j][1] * i0;
        float v10 = Oa[j][2] * i1, v11 = Oa[j][3] * i1;
        __half h00, l00, h01, l01, h10, l10, h11, l11;
        hsplit(v00, h00, l00); hsplit(v01, h01, l01);
        hsplit(v10, h10, l10); hsplit(v11, h11, l11);
        *(__half2*)(Ch + base0 + d0) = __halves2half2(h00, h01);
        *(__half2*)(Cl + base0 + d0) = __halves2half2(l00, l01);
        *(__half2*)(Ch + base1 + d0) = __halves2half2(h10, h11);
        *(__half2*)(Cl + base1 + d0) = __halves2half2(l10, l11);
    }
}

// ---------------------------------------------------------------------------
extern "C" void kernel_launch(void* const* d_in, const int* in_sizes, int n_in,
                              void* d_out, int out_size)
{
    const float* query = (const float*)d_in[0];
    const float* key   = (const float*)d_in[1];
    const float* value = (const float*)d_in[2];
    const int*   mask  = (const int*)d_in[3];
    const float* wq = (const float*)d_in[4];  const float* bq = (const float*)d_in[5];
    const float* wk = (const float*)d_in[6];  const float* bk = (const float*)d_in[7];
    const float* wv = (const float*)d_in[8];  const float* bv = (const float*)d_in[9];
    const float* wo = (const float*)d_in[10]; const float* bo = (const float*)d_in[11];

    #define SYM(p, sname) void* p; cudaGetSymbolAddress(&p, sname)
    SYM(xh, g_xh); SYM(xl, g_xl); SYM(wh, g_wh);
    SYM(qh, g_qh); SYM(ql, g_ql); SYM(kh, g_kh); SYM(vth, g_vth);
    SYM(ch, g_ch); SYM(cl, g_cl);
    #undef SYM
    typedef __half hf;

    const int GEMM_SMEM = 3 * GSTG * (int)sizeof(hf);   // 92160
    static bool init = false;
    if (!init) {
        cudaFuncSetAttribute(flash_attn, cudaFuncAttributeMaxDynamicSharedMemorySize,
                             FA_SMEM);
        cudaFuncSetAttribute(gemm_fp16<1>, cudaFuncAttributeMaxDynamicSharedMemorySize,
                             GEMM_SMEM);
        cudaFuncSetAttribute(gemm_fp16<0>, cudaFuncAttributeMaxDynamicSharedMemorySize,
                             GEMM_SMEM);
        init = true;
    }

    // 1) splits: inputs hi/lo, weights hi-only
    split_in<<<dim3(NELEM / 4 / 256, 3), 256>>>(
        (const float4*)query, (const float4*)key, (const float4*)value,
        (uint2*)xh, (uint2*)xl, NELEM / 4);
    conv_w<<<dim3(WELEM / 4 / 256, 4), 256>>>(
        (const float4*)wq, (const float4*)wk, (const float4*)wv, (const float4*)wo,
        (uint2*)wh, WELEM / 4);

    // 2) Q/K/V projections
    gemm_fp16<1><<<dim3(8, 32, 3), 256, GEMM_SMEM>>>(
        (hf*)xh, (hf*)xl, (hf*)wh, bq, bk, bv,
        nullptr, (hf*)qh, (hf*)ql, (hf*)kh, (hf*)vth);

    // 3) fused flash attention
    flash_attn<<<dim3(SEQ / 128, ZH), 256, FA_SMEM>>>(
        (hf*)qh, (hf*)ql, (hf*)kh, (hf*)vth, mask, (hf*)ch, (hf*)cl);

    // 4) output projection
    gemm_fp16<0><<<dim3(8, 32, 1), 256, GEMM_SMEM>>>(
        (hf*)ch, (hf*)cl, (hf*)wh + 3 * (size_t)WELEM, bo, nullptr, nullptr,
        (float*)d_out, nullptr, nullptr, nullptr, nullptr);
}

// round 16
// speedup vs baseline: 1.9907x; 1.2211x over previous
#include <cuda_runtime.h>
#include <cuda_fp16.h>
#include <math.h>
#include <stdint.h>

#define SEQ   2048
#define DM    1024
#define NH    16
#define HD    64
#define MROWS 4096
#define ZH    32
#define NELEM (MROWS*DM)      // 4M
#define WELEM (DM*DM)         // 1M

// Q pre-scale: (1/sqrt(64)) * log2(e)  -> softmax done in exp2 domain
#define QSCALE 0.18033688011f

// ---------------------------------------------------------------------------
// Scratch (__device__ globals; no allocations allowed)
// ---------------------------------------------------------------------------
__device__ __half g_xh[3*NELEM];                  // inputs (q,k,v) fp16
__device__ __half g_wh[4*WELEM];                  // weights fp16 (B-side)
__device__ __half g_qh[NELEM], g_ql[NELEM];       // projected Q hi/lo (pre-scaled)
__device__ __half g_kh[NELEM];                    // projected K
__device__ __half g_vth[ZH*HD*SEQ];               // projected V^T per head
__device__ __half g_ch[NELEM], g_cl[NELEM];       // context hi/lo

// ---------------------------------------------------------------------------
// PTX helpers
// ---------------------------------------------------------------------------
__device__ __forceinline__ uint32_t su32(const void* p) {
    uint32_t a;
    asm("{ .reg .u64 t; cvta.to.shared.u64 t, %1; cvt.u32.u64 %0, t; }" : "=r"(a) : "l"(p));
    return a;
}
#define CPASYNC(d, s) asm volatile("cp.async.cg.shared.global [%0], [%1], 16;" :: "r"(d), "l"(s))
#define CPCOMMIT()    asm volatile("cp.async.commit_group;")
#define CPWAIT0()     asm volatile("cp.async.wait_group 0;")
#define CPWAIT1()     asm volatile("cp.async.wait_group 1;")
#define CPWAIT2()     asm volatile("cp.async.wait_group 2;")

__device__ __forceinline__ void ldm4(uint32_t* r, uint32_t addr) {
    asm volatile("ldmatrix.sync.aligned.m8n8.x4.shared.b16 {%0,%1,%2,%3}, [%4];"
                 : "=r"(r[0]), "=r"(r[1]), "=r"(r[2]), "=r"(r[3]) : "r"(addr));
}
__device__ __forceinline__ void mma16816(float* c, const uint32_t* a, uint32_t b0, uint32_t b1) {
    asm volatile("mma.sync.aligned.m16n8k16.row.col.f32.f16.f16.f32 "
                 "{%0,%1,%2,%3}, {%4,%5,%6,%7}, {%8,%9}, {%0,%1,%2,%3};"
                 : "+f"(c[0]), "+f"(c[1]), "+f"(c[2]), "+f"(c[3])
                 : "r"(a[0]), "r"(a[1]), "r"(a[2]), "r"(a[3]), "r"(b0), "r"(b1));
}
__device__ __forceinline__ uint32_t pk2(float lo, float hi) {   // {lo@0-15, hi@16-31}
    uint32_t r;
    asm("cvt.rn.f16x2.f32 %0, %1, %2;" : "=r"(r) : "f"(hi), "f"(lo));
    return r;
}
__device__ __forceinline__ float ex2(float x) {                 // raw MUFU.EX2
    float y;
    asm("ex2.approx.ftz.f32 %0, %1;" : "=f"(y) : "f"(x));
    return y;
}
__device__ __forceinline__ void hsplit(float x, __half& h, __half& l) {
    h = __float2half_rn(x);
    l = __float2half_rn(x - __half2float(h));
}

// ---------------------------------------------------------------------------
// fp32 -> fp16 convert-only: inputs (grid.y 0..2) and weights (grid.y 3..6)
// ---------------------------------------------------------------------------
__global__ void __launch_bounds__(256)
conv_all(const float4* __restrict__ q, const float4* __restrict__ k,
         const float4* __restrict__ v,
         const float4* __restrict__ wq, const float4* __restrict__ wk,
         const float4* __restrict__ wv, const float4* __restrict__ wo,
         uint2* __restrict__ xh, uint2* __restrict__ wh)
{
    int i = blockIdx.x * 256 + threadIdx.x;
    int y = blockIdx.y;
    const float4* src;
    uint2* dst;
    int n4;
    if (y < 3) {
        src = (y == 0) ? q : (y == 1) ? k : v;
        dst = xh + (size_t)y * (NELEM / 4);
        n4 = NELEM / 4;
    } else {
        int w = y - 3;
        src = (w == 0) ? wq : (w == 1) ? wk : (w == 2) ? wv : wo;
        dst = wh + (size_t)w * (WELEM / 4);
        n4 = WELEM / 4;
    }
    if (i >= n4) return;
    float4 x = src[i];
    uint2 h;
    h.x = pk2(x.x, x.y); h.y = pk2(x.z, x.w);
    dst[i] = h;
}

#define GPL 5120   // halves per plane (128 x 40)

// ---------------------------------------------------------------------------
// fp16 GEMM: C = A @ Bh^T (+bias). 128x128 tile, BK=32, triple-buffered,
// 2 CTAs/SM.  TERMS=1: A = Ah.  TERMS=2: A = Ah + Al.
// QKV=1: grid (8,32,3): z=0 Q (scaled hi/lo out), z=1 K, z=2 V (transposed)
// QKV=0: out-projection (ctx hi/lo in, fp32 out)
// ---------------------------------------------------------------------------
template<int QKV, int TERMS>
__global__ void __launch_bounds__(256, 2)
gemm_fp16(const __half* __restrict__ Xh, const __half* __restrict__ Xl,
          const __half* __restrict__ Wh,
          const float* __restrict__ bq, const float* __restrict__ bk,
          const float* __restrict__ bv,
          float* __restrict__ Outf,
          __half* __restrict__ qh, __half* __restrict__ ql,
          __half* __restrict__ kh, __half* __restrict__ vth)
{
    extern __shared__ __align__(16) __half gsm[];
    const int STG = (TERMS + 1) * GPL;     // halves per pipeline stage

    const int tid = threadIdx.x, lane = tid & 31, wid = tid >> 5;
    const int m0 = blockIdx.y * 128, n0 = blockIdx.x * 128;
    const int z = QKV ? blockIdx.z : 0;

    const __half* Ahp = Xh + (QKV ? (size_t)z * NELEM : 0) + (size_t)m0 * DM;
    const __half* Alp = (TERMS == 2) ? Xl + (size_t)m0 * DM : nullptr;
    const __half* Bhp = Wh + (QKV ? (size_t)z * WELEM : 0) + (size_t)n0 * DM;
    const float* Bi = QKV ? ((z == 0) ? bq : (z == 1) ? bk : bv) : bq;

    auto loadTile = [&](int kt, int st) {
        const int kb = kt * 32;
        const int r = tid >> 1, c0 = (tid & 1) * 16;
        __half* ah = gsm + st * STG;
        __half* bh = ah + TERMS * GPL;
        CPASYNC(su32(&ah[r * 40 + c0]),     Ahp + (size_t)r * DM + kb + c0);
        CPASYNC(su32(&ah[r * 40 + c0 + 8]), Ahp + (size_t)r * DM + kb + c0 + 8);
        if (TERMS == 2) {
            __half* al = ah + GPL;
            CPASYNC(su32(&al[r * 40 + c0]),     Alp + (size_t)r * DM + kb + c0);
            CPASYNC(su32(&al[r * 40 + c0 + 8]), Alp + (size_t)r * DM + kb + c0 + 8);
        }
        CPASYNC(su32(&bh[r * 40 + c0]),     Bhp + (size_t)r * DM + kb + c0);
        CPASYNC(su32(&bh[r * 40 + c0 + 8]), Bhp + (size_t)r * DM + kb + c0 + 8);
    };

    const int wm = wid >> 1, wn = wid & 1;
    float acc[2][8][4];
    #pragma unroll
    for (int i = 0; i < 2; i++)
        #pragma unroll
        for (int j = 0; j < 8; j++)
            #pragma unroll
            for (int t = 0; t < 4; t++) acc[i][j][t] = 0.f;

    const int frow = ((lane >> 3) & 1) * 8 + (lane & 7);
    const int fcol = ((lane >> 4) & 1) * 8;

    loadTile(0, 0); CPCOMMIT();
    loadTile(1, 1); CPCOMMIT();

    int st = 0;
    for (int kt = 0; kt < 32; kt++) {
        if (kt + 2 < 32) {
            int stl = st + 2; if (stl >= 3) stl -= 3;
            loadTile(kt + 2, stl); CPCOMMIT(); CPWAIT2();
        } else if (kt + 1 < 32) {
            CPWAIT1();
        } else {
            CPWAIT0();
        }
        __syncthreads();

        const __half* ah = gsm + st * STG;
        const __half* al = ah + GPL;
        const __half* bh = ah + TERMS * GPL;
        #pragma unroll
        for (int k16 = 0; k16 < 2; k16++) {
            uint32_t a_h[2][4], a_l[2][4];
            #pragma unroll
            for (int i = 0; i < 2; i++) {
                ldm4(a_h[i], su32(&ah[(wm * 32 + i * 16 + frow) * 40 + k16 * 16 + fcol]));
                if (TERMS == 2)
                    ldm4(a_l[i], su32(&al[(wm * 32 + i * 16 + frow) * 40 + k16 * 16 + fcol]));
            }
            #pragma unroll
            for (int j = 0; j < 4; j++) {
                uint32_t b_h[4];
                ldm4(b_h, su32(&bh[(wn * 64 + j * 16 + frow) * 40 + k16 * 16 + fcol]));
                #pragma unroll
                for (int i = 0; i < 2; i++) {
                    mma16816(acc[i][2 * j],     a_h[i], b_h[0], b_h[2]);
                    mma16816(acc[i][2 * j + 1], a_h[i], b_h[1], b_h[3]);
                    if (TERMS == 2) {
                        mma16816(acc[i][2 * j],     a_l[i], b_h[0], b_h[2]);
                        mma16816(acc[i][2 * j + 1], a_l[i], b_h[1], b_h[3]);
                    }
                }
            }
        }
        __syncthreads();
        if (++st >= 3) st = 0;
    }

    const int er = lane >> 2, ec = (lane & 3) * 2;
    #pragma unroll
    for (int i = 0; i < 2; i++) {
        #pragma unroll
        for (int j = 0; j < 8; j++) {
            #pragma unroll
            for (int h2 = 0; h2 < 2; h2++) {
                int rr = m0 + wm * 32 + i * 16 + er + h2 * 8;
                int nb = n0 + wn * 64 + j * 8 + ec;
                #pragma unroll
                for (int t = 0; t < 2; t++) {
                    int n = nb + t;
                    float x = acc[i][j][h2 * 2 + t] + Bi[n];
                    if (!QKV) {
                        Outf[(size_t)rr * DM + n] = x;
                    } else if (z == 0) {
                        x *= QSCALE;
                        __half h, l; hsplit(x, h, l);
                        qh[(size_t)rr * DM + n] = h; ql[(size_t)rr * DM + n] = l;
                    } else if (z == 1) {
                        kh[(size_t)rr * DM + n] = __float2half_rn(x);
                    } else {
                        int hd = n >> 6, d = n & 63;
                        int zz = (rr >> 11) * NH + hd, s = rr & 2047;
                        vth[(size_t)zz * HD * SEQ + (size_t)d * SEQ + s] = __float2half_rn(x);
                    }
                }
            }
        }
    }
}

// ---------------------------------------------------------------------------
// Fused flash attention. Block = 128 queries x 1 head, 2 CTAs/SM.
// Scores pre-scaled to exp2 domain (QSCALE). S = (Qh+Ql)·Kh^T, PV = Ph·Vh.
// Triple-buffered K/V; O-rescale skipped when running max unchanged.
// ---------------------------------------------------------------------------
#define FA_QS    0                        // Q: 128 x 136 halves
#define FA_KS    17408                    // K: 3 x 64 x 72
#define FA_VS    31232                    // V: 3 x 64 x 72
#define FA_MB_B  90112                    // bitmap: 64 u32
#define FA_FLG_B 90368                    // flags: 32 int
#define FA_SMEM  90496

__global__ void __launch_bounds__(256, 2)
flash_attn(const __half* __restrict__ Qh, const __half* __restrict__ Ql,
           const __half* __restrict__ Kh, const __half* __restrict__ Vh,
           const int* __restrict__ mask,
           __half* __restrict__ Ch, __half* __restrict__ Cl)
{
    extern __shared__ __align__(16) __half sm[];
    __half* Qs = sm + FA_QS;
    __half* Ks = sm + FA_KS;
    __half* Vs = sm + FA_VS;
    uint32_t* mb = (uint32_t*)((char*)sm + FA_MB_B);
    int* flg = (int*)((char*)sm + FA_FLG_B);

    const int tid = threadIdx.x, lane = tid & 31, w = tid >> 5;
    const int qb = blockIdx.x, z = blockIdx.y;
    const int b = z >> 4, h = z & 15;

    const __half* Qhp = Qh + ((size_t)(b * SEQ + qb * 128)) * DM + h * HD;
    const __half* Qlp = Ql + ((size_t)(b * SEQ + qb * 128)) * DM + h * HD;
    const __half* Khp = Kh + ((size_t)(b * SEQ)) * DM + h * HD;
    const __half* Vhp = Vh + (size_t)z * HD * SEQ;

    if (tid < 32) flg[tid] = 0;
    __syncthreads();
    #pragma unroll
    for (int i = 0; i < 8; i++) {
        int k = i * 256 + tid;
        int m = mask[b * SEQ + k];
        uint32_t bits = __ballot_sync(0xffffffffu, m != 0);
        if (lane == 0) {
            mb[k >> 5] = bits;
            if (bits != 0xffffffffu) flg[k >> 6] = 1;
        }
    }

    // Q tile: 128 rows x (64 hi | 64 lo)
    {
        int r = tid >> 1, q = tid & 1;
        #pragma unroll
        for (int i = 0; i < 4; i++) {
            int cc = (q + i * 2) * 8;
            CPASYNC(su32(Qs + r * 136 + cc),      Qhp + (size_t)r * DM + cc);
            CPASYNC(su32(Qs + r * 136 + 64 + cc), Qlp + (size_t)r * DM + cc);
        }
    }
    auto loadKV = [&](int kb, int st) {
        int r = tid >> 2, q = tid & 3;
        #pragma unroll
        for (int i = 0; i < 2; i++) {
            int cc = (q + i * 4) * 8;
            CPASYNC(su32(Ks + st * 4608 + r * 72 + cc),
                    Khp + (size_t)(kb * 64 + r) * DM + cc);
            CPASYNC(su32(Vs + st * 4608 + r * 72 + cc),
                    Vhp + (size_t)r * SEQ + kb * 64 + cc);
        }
    };
    loadKV(0, 0); CPCOMMIT();
    loadKV(1, 1); CPCOMMIT();

    const int frow = ((lane >> 3) & 1) * 8 + (lane & 7);
    const int fcol = ((lane >> 4) & 1) * 8;
    const int er = lane >> 2, ec = (lane & 3) * 2;

    float Oa[8][4];
    #pragma unroll
    for (int j = 0; j < 8; j++)
        #pragma unroll
        for (int t = 0; t < 4; t++) Oa[j][t] = 0.f;
    float mrow[2] = { -1e30f, -1e30f }, lrow[2] = { 0.f, 0.f };

    int st = 0;
    for (int kb = 0; kb < 32; kb++) {
        if (kb + 2 < 32) {
            int stl = st + 2; if (stl >= 3) stl -= 3;
            loadKV(kb + 2, stl); CPCOMMIT(); CPWAIT2();
        } else if (kb + 1 < 32) {
            CPWAIT1();
        } else {
            CPWAIT0();
        }
        __syncthreads();

        // ---- S = Qh·Kh + Ql·Kh (16 x 64 per warp, exp2 domain) ----
        float Sa[8][4];
        #pragma unroll
        for (int j = 0; j < 8; j++)
            #pragma unroll
            for (int t = 0; t < 4; t++) Sa[j][t] = 0.f;

        const __half* kbuf = Ks + st * 4608;
        #pragma unroll
        for (int k = 0; k < 4; k++) {
            uint32_t qhf[4], qlf[4];
            ldm4(qhf, su32(Qs + (w * 16 + frow) * 136 + k * 16 + fcol));
            ldm4(qlf, su32(Qs + (w * 16 + frow) * 136 + 64 + k * 16 + fcol));
            #pragma unroll
            for (int j = 0; j < 4; j++) {
                uint32_t b4[4];
                ldm4(b4, su32(kbuf + (j * 16 + frow) * 72 + k * 16 + fcol));
                mma16816(Sa[2 * j],     qhf, b4[0], b4[2]);
                mma16816(Sa[2 * j + 1], qhf, b4[1], b4[3]);
                mma16816(Sa[2 * j],     qlf, b4[0], b4[2]);
                mma16816(Sa[2 * j + 1], qlf, b4[1], b4[3]);
            }
        }

        // ---- mask (bitmap) ----
        if (flg[kb]) {
            #pragma unroll
            for (int j = 0; j < 8; j++) {
                int c0 = kb * 64 + j * 8 + ec;
                if (!((mb[c0 >> 5] >> (c0 & 31)) & 1u))         { Sa[j][0] = -1e9f; Sa[j][2] = -1e9f; }
                if (!((mb[(c0+1) >> 5] >> ((c0+1) & 31)) & 1u)) { Sa[j][1] = -1e9f; Sa[j][3] = -1e9f; }
            }
        }

        // ---- online softmax: max + exp2 (rows er, er+8) ----
        float mx0 = -1e30f, mx1 = -1e30f;
        #pragma unroll
        for (int j = 0; j < 8; j++) {
            mx0 = fmaxf(mx0, fmaxf(Sa[j][0], Sa[j][1]));
            mx1 = fmaxf(mx1, fmaxf(Sa[j][2], Sa[j][3]));
        }
        #pragma unroll
        for (int o = 1; o <= 2; o <<= 1) {
            mx0 = fmaxf(mx0, __shfl_xor_sync(0xffffffffu, mx0, o));
            mx1 = fmaxf(mx1, __shfl_xor_sync(0xffffffffu, mx1, o));
        }
        float nm0 = fmaxf(mrow[0], mx0), nm1 = fmaxf(mrow[1], mx1);
        float cor0 = ex2(mrow[0] - nm0), cor1 = ex2(mrow[1] - nm1);
        mrow[0] = nm0; mrow[1] = nm1;

        #pragma unroll
        for (int j = 0; j < 8; j++) {
            Sa[j][0] = ex2(Sa[j][0] - nm0);
            Sa[j][1] = ex2(Sa[j][1] - nm0);
            Sa[j][2] = ex2(Sa[j][2] - nm1);
            Sa[j][3] = ex2(Sa[j][3] - nm1);
        }

        // ---- rescale O only if some row max moved (warp-uniform check) ----
        bool nochg = __all_sync(0xffffffffu, (cor0 == 1.f) && (cor1 == 1.f));
        if (!nochg) {
            #pragma unroll
            for (int j = 0; j < 8; j++) {
                Oa[j][0] *= cor0; Oa[j][1] *= cor0;
                Oa[j][2] *= cor1; Oa[j][3] *= cor1;
            }
        }

        // ---- PV: O += Ph·Vh ----
        const __half* vbuf = Vs + st * 4608;
        #pragma unroll
        for (int c = 0; c < 4; c++) {
            uint32_t ph[4];
            ph[0] = pk2(Sa[2*c][0],   Sa[2*c][1]);
            ph[1] = pk2(Sa[2*c][2],   Sa[2*c][3]);
            ph[2] = pk2(Sa[2*c+1][0], Sa[2*c+1][1]);
            ph[3] = pk2(Sa[2*c+1][2], Sa[2*c+1][3]);
            #pragma unroll
            for (int t = 0; t < 4; t++) {
                uint32_t v4[4];
                ldm4(v4, su32(vbuf + (t * 16 + frow) * 72 + c * 16 + fcol));
                mma16816(Oa[2 * t],     ph, v4[0], v4[2]);
                mma16816(Oa[2 * t + 1], ph, v4[1], v4[3]);
            }
        }

        // ---- l-sum after PV (latency hidden under MMAs) ----
        float rs0 = 0.f, rs1 = 0.f;
        #pragma unroll
        for (int j = 0; j < 8; j++) {
            rs0 += Sa[j][0] + Sa[j][1];
            rs1 += Sa[j][2] + Sa[j][3];
        }
        #pragma unroll
        for (int o = 1; o <= 2; o <<= 1) {
            rs0 += __shfl_xor_sync(0xffffffffu, rs0, o);
            rs1 += __shfl_xor_sync(0xffffffffu, rs1, o);
        }
        lrow[0] = lrow[0] * cor0 + rs0;
        lrow[1] = lrow[1] * cor1 + rs1;

        __syncthreads();
        if (++st >= 3) st = 0;
    }

    // ---- epilogue: normalize, write ctx hi/lo ----
    float i0 = 1.f / lrow[0], i1 = 1.f / lrow[1];
    int r0g = b * SEQ + qb * 128 + w * 16 + er;
    size_t base0 = (size_t)r0g * DM + h * HD;
    size_t base1 = base0 + (size_t)8 * DM;
    #pragma unroll
    for (int j = 0; j < 8; j++) {
        int d0 = j * 8 + ec;
        float v00 = Oa[j][0] * i0, v01 = Oa[j][1] * i0;
        float v10 = Oa[j][2] * i1, v11 = Oa[j][3] * i1;
        __half h00, l00, h01, l01, h10, l10, h11, l11;
        hsplit(v00, h00, l00); hsplit(v01, h01, l01);
        hsplit(v10, h10, l10); hsplit(v11, h11, l11);
        *(__half2*)(Ch + base0 + d0) = __halves2half2(h00, h01);
        *(__half2*)(Cl + base0 + d0) = __halves2half2(l00, l01);
        *(__half2*)(Ch + base1 + d0) = __halves2half2(h10, h11);
        *(__half2*)(Cl + base1 + d0) = __halves2half2(l10, l11);
    }
}

// ---------------------------------------------------------------------------
extern "C" void kernel_launch(void* const* d_in, const int* in_sizes, int n_in,
                              void* d_out, int out_size)
{
    const float* query = (const float*)d_in[0];
    const float* key   = (const float*)d_in[1];
    const float* value = (const float*)d_in[2];
    const int*   mask  = (const int*)d_in[3];
    const float* wq = (const float*)d_in[4];  const float* bq = (const float*)d_in[5];
    const float* wk = (const float*)d_in[6];  const float* bk = (const float*)d_in[7];
    const float* wv = (const float*)d_in[8];  const float* bv = (const float*)d_in[9];
    const float* wo = (const float*)d_in[10]; const float* bo = (const float*)d_in[11];

    #define SYM(p, sname) void* p; cudaGetSymbolAddress(&p, sname)
    SYM(xh, g_xh); SYM(wh, g_wh);
    SYM(qh, g_qh); SYM(ql, g_ql); SYM(kh, g_kh); SYM(vth, g_vth);
    SYM(ch, g_ch); SYM(cl, g_cl);
    #undef SYM
    typedef __half hf;

    const int QKV_SMEM = 3 * 2 * GPL * (int)sizeof(hf);   // 61440 (ah+bh)
    const int OP_SMEM  = 3 * 3 * GPL * (int)sizeof(hf);   // 92160 (ah+al+bh)
    static bool init = false;
    if (!init) {
        cudaFuncSetAttribute(flash_attn, cudaFuncAttributeMaxDynamicSharedMemorySize,
                             FA_SMEM);
        cudaFuncSetAttribute((gemm_fp16<1,1>), cudaFuncAttributeMaxDynamicSharedMemorySize,
                             QKV_SMEM);
        cudaFuncSetAttribute((gemm_fp16<0,2>), cudaFuncAttributeMaxDynamicSharedMemorySize,
                             OP_SMEM);
        init = true;
    }

    // 1) convert inputs + weights to fp16 (one fused launch)
    conv_all<<<dim3(NELEM / 4 / 256, 7), 256>>>(
        (const float4*)query, (const float4*)key, (const float4*)value,
        (const float4*)wq, (const float4*)wk, (const float4*)wv, (const float4*)wo,
        (uint2*)xh, (uint2*)wh);

    // 2) Q/K/V projections (1-term)
    gemm_fp16<1,1><<<dim3(8, 32, 3), 256, QKV_SMEM>>>(
        (hf*)xh, nullptr, (hf*)wh, bq, bk, bv,
        nullptr, (hf*)qh, (hf*)ql, (hf*)kh, (hf*)vth);

    // 3) fused flash attention
    flash_attn<<<dim3(SEQ / 128, ZH), 256, FA_SMEM>>>(
        (hf*)qh, (hf*)ql, (hf*)kh, (hf*)vth, mask, (hf*)ch, (hf*)cl);

    // 4) output projection (2-term ctx)
    gemm_fp16<0,2><<<dim3(8, 32, 1), 256, OP_SMEM>>>(
        (hf*)ch, (hf*)cl, (hf*)wh + 3 * (size_t)WELEM, bo, nullptr, nullptr,
        (float*)d_out, nullptr, nullptr, nullptr, nullptr);
}

// round 17
// speedup vs baseline: 2.1716x; 1.0909x over previous
#include <cuda_runtime.h>
#include <cuda_fp16.h>
#include <math.h>
#include <stdint.h>

#define SEQ   2048
#define DM    1024
#define NH    16
#define HD    64
#define MROWS 4096
#define ZH    32
#define NELEM (MROWS*DM)      // 4M
#define WELEM (DM*DM)         // 1M

// Q pre-scale: (1/sqrt(64)) * log2(e)  -> softmax done in exp2 domain
#define QSCALE 0.18033688011f

// ---------------------------------------------------------------------------
// Scratch (__device__ globals; no allocations allowed)
// ---------------------------------------------------------------------------
__device__ __half g_xh[3*NELEM];                  // inputs (q,k,v) fp16
__device__ __half g_wh[4*WELEM];                  // weights fp16 (B-side)
__device__ __half g_qh[NELEM], g_ql[NELEM];       // projected Q hi/lo (pre-scaled)
__device__ __half g_kh[NELEM];                    // projected K
__device__ __half g_vth[ZH*HD*SEQ];               // projected V^T per head
__device__ __half g_ch[NELEM];                    // context (fp16, 1-term)

// ---------------------------------------------------------------------------
// PTX helpers
// ---------------------------------------------------------------------------
__device__ __forceinline__ uint32_t su32(const void* p) {
    uint32_t a;
    asm("{ .reg .u64 t; cvta.to.shared.u64 t, %1; cvt.u32.u64 %0, t; }" : "=r"(a) : "l"(p));
    return a;
}
#define CPASYNC(d, s) asm volatile("cp.async.cg.shared.global [%0], [%1], 16;" :: "r"(d), "l"(s))
#define CPCOMMIT()    asm volatile("cp.async.commit_group;")
#define CPWAIT0()     asm volatile("cp.async.wait_group 0;")
#define CPWAIT1()     asm volatile("cp.async.wait_group 1;")
#define CPWAIT2()     asm volatile("cp.async.wait_group 2;")

__device__ __forceinline__ void ldm4(uint32_t* r, uint32_t addr) {
    asm volatile("ldmatrix.sync.aligned.m8n8.x4.shared.b16 {%0,%1,%2,%3}, [%4];"
                 : "=r"(r[0]), "=r"(r[1]), "=r"(r[2]), "=r"(r[3]) : "r"(addr));
}
__device__ __forceinline__ void mma16816(float* c, const uint32_t* a, uint32_t b0, uint32_t b1) {
    asm volatile("mma.sync.aligned.m16n8k16.row.col.f32.f16.f16.f32 "
                 "{%0,%1,%2,%3}, {%4,%5,%6,%7}, {%8,%9}, {%0,%1,%2,%3};"
                 : "+f"(c[0]), "+f"(c[1]), "+f"(c[2]), "+f"(c[3])
                 : "r"(a[0]), "r"(a[1]), "r"(a[2]), "r"(a[3]), "r"(b0), "r"(b1));
}
__device__ __forceinline__ uint32_t pk2(float lo, float hi) {   // {lo@0-15, hi@16-31}
    uint32_t r;
    asm("cvt.rn.f16x2.f32 %0, %1, %2;" : "=r"(r) : "f"(hi), "f"(lo));
    return r;
}
__device__ __forceinline__ float ex2(float x) {                 // raw MUFU.EX2
    float y;
    asm("ex2.approx.ftz.f32 %0, %1;" : "=f"(y) : "f"(x));
    return y;
}
__device__ __forceinline__ void hsplit(float x, __half& h, __half& l) {
    h = __float2half_rn(x);
    l = __float2half_rn(x - __half2float(h));
}

// ---------------------------------------------------------------------------
// fp32 -> fp16 convert-only: inputs (grid.y 0..2) and weights (grid.y 3..6)
// ---------------------------------------------------------------------------
__global__ void __launch_bounds__(256)
conv_all(const float4* __restrict__ q, const float4* __restrict__ k,
         const float4* __restrict__ v,
         const float4* __restrict__ wq, const float4* __restrict__ wk,
         const float4* __restrict__ wv, const float4* __restrict__ wo,
         uint2* __restrict__ xh, uint2* __restrict__ wh)
{
    int i = blockIdx.x * 256 + threadIdx.x;
    int y = blockIdx.y;
    const float4* src;
    uint2* dst;
    int n4;
    if (y < 3) {
        src = (y == 0) ? q : (y == 1) ? k : v;
        dst = xh + (size_t)y * (NELEM / 4);
        n4 = NELEM / 4;
    } else {
        int w = y - 3;
        src = (w == 0) ? wq : (w == 1) ? wk : (w == 2) ? wv : wo;
        dst = wh + (size_t)w * (WELEM / 4);
        n4 = WELEM / 4;
    }
    if (i >= n4) return;
    float4 x = src[i];
    uint2 h;
    h.x = pk2(x.x, x.y); h.y = pk2(x.z, x.w);
    dst[i] = h;
}

#define GPL 5120   // halves per plane (128 x 40)

// ---------------------------------------------------------------------------
// fp16 1-term GEMM: C = A @ Bh^T (+bias). 128x128 tile, BK=32, triple-buffered,
// 2 CTAs/SM.
// QKV=1: grid (8,32,3): z=0 Q (scaled hi/lo out), z=1 K, z=2 V (transposed)
// QKV=0: out-projection (ctx fp16 in, fp32 out)
// ---------------------------------------------------------------------------
template<int QKV>
__global__ void __launch_bounds__(256, 2)
gemm_fp16(const __half* __restrict__ Xh, const __half* __restrict__ Wh,
          const float* __restrict__ bq, const float* __restrict__ bk,
          const float* __restrict__ bv,
          float* __restrict__ Outf,
          __half* __restrict__ qh, __half* __restrict__ ql,
          __half* __restrict__ kh, __half* __restrict__ vth)
{
    extern __shared__ __align__(16) __half gsm[];
    const int STG = 2 * GPL;               // halves per pipeline stage (ah + bh)

    const int tid = threadIdx.x, lane = tid & 31, wid = tid >> 5;
    const int m0 = blockIdx.y * 128, n0 = blockIdx.x * 128;
    const int z = QKV ? blockIdx.z : 0;

    const __half* Ahp = Xh + (QKV ? (size_t)z * NELEM : 0) + (size_t)m0 * DM;
    const __half* Bhp = Wh + (QKV ? (size_t)z * WELEM : 0) + (size_t)n0 * DM;
    const float* Bi = QKV ? ((z == 0) ? bq : (z == 1) ? bk : bv) : bq;

    auto loadTile = [&](int kt, int st) {
        const int kb = kt * 32;
        const int r = tid >> 1, c0 = (tid & 1) * 16;
        __half* ah = gsm + st * STG;
        __half* bh = ah + GPL;
        CPASYNC(su32(&ah[r * 40 + c0]),     Ahp + (size_t)r * DM + kb + c0);
        CPASYNC(su32(&ah[r * 40 + c0 + 8]), Ahp + (size_t)r * DM + kb + c0 + 8);
        CPASYNC(su32(&bh[r * 40 + c0]),     Bhp + (size_t)r * DM + kb + c0);
        CPASYNC(su32(&bh[r * 40 + c0 + 8]), Bhp + (size_t)r * DM + kb + c0 + 8);
    };

    const int wm = wid >> 1, wn = wid & 1;
    float acc[2][8][4];
    #pragma unroll
    for (int i = 0; i < 2; i++)
        #pragma unroll
        for (int j = 0; j < 8; j++)
            #pragma unroll
            for (int t = 0; t < 4; t++) acc[i][j][t] = 0.f;

    const int frow = ((lane >> 3) & 1) * 8 + (lane & 7);
    const int fcol = ((lane >> 4) & 1) * 8;

    loadTile(0, 0); CPCOMMIT();
    loadTile(1, 1); CPCOMMIT();

    int st = 0;
    for (int kt = 0; kt < 32; kt++) {
        if (kt + 2 < 32) {
            int stl = st + 2; if (stl >= 3) stl -= 3;
            loadTile(kt + 2, stl); CPCOMMIT(); CPWAIT2();
        } else if (kt + 1 < 32) {
            CPWAIT1();
        } else {
            CPWAIT0();
        }
        __syncthreads();

        const __half* ah = gsm + st * STG;
        const __half* bh = ah + GPL;
        #pragma unroll
        for (int k16 = 0; k16 < 2; k16++) {
            uint32_t a_h[2][4];
            #pragma unroll
            for (int i = 0; i < 2; i++)
                ldm4(a_h[i], su32(&ah[(wm * 32 + i * 16 + frow) * 40 + k16 * 16 + fcol]));
            #pragma unroll
            for (int j = 0; j < 4; j++) {
                uint32_t b_h[4];
                ldm4(b_h, su32(&bh[(wn * 64 + j * 16 + frow) * 40 + k16 * 16 + fcol]));
                #pragma unroll
                for (int i = 0; i < 2; i++) {
                    mma16816(acc[i][2 * j],     a_h[i], b_h[0], b_h[2]);
                    mma16816(acc[i][2 * j + 1], a_h[i], b_h[1], b_h[3]);
                }
            }
        }
        __syncthreads();
        if (++st >= 3) st = 0;
    }

    const int er = lane >> 2, ec = (lane & 3) * 2;
    #pragma unroll
    for (int i = 0; i < 2; i++) {
        #pragma unroll
        for (int j = 0; j < 8; j++) {
            #pragma unroll
            for (int h2 = 0; h2 < 2; h2++) {
                int rr = m0 + wm * 32 + i * 16 + er + h2 * 8;
                int nb = n0 + wn * 64 + j * 8 + ec;
                #pragma unroll
                for (int t = 0; t < 2; t++) {
                    int n = nb + t;
                    float x = acc[i][j][h2 * 2 + t] + Bi[n];
                    if (!QKV) {
                        Outf[(size_t)rr * DM + n] = x;
                    } else if (z == 0) {
                        x *= QSCALE;
                        __half h, l; hsplit(x, h, l);
                        qh[(size_t)rr * DM + n] = h; ql[(size_t)rr * DM + n] = l;
                    } else if (z == 1) {
                        kh[(size_t)rr * DM + n] = __float2half_rn(x);
                    } else {
                        int hd = n >> 6, d = n & 63;
                        int zz = (rr >> 11) * NH + hd, s = rr & 2047;
                        vth[(size_t)zz * HD * SEQ + (size_t)d * SEQ + s] = __float2half_rn(x);
                    }
                }
            }
        }
    }
}

// ---------------------------------------------------------------------------
// Fused flash attention. Block = 128 queries x 1 head, 2 CTAs/SM.
// Scores pre-scaled to exp2 domain (QSCALE). S = (Qh+Ql)·Kh^T, PV = Ph·Vh.
// Triple-buffered K/V; O-rescale skipped when running max unchanged.
// ctx written as fp16 (1-term, consumed by 1-term oproj).
// ---------------------------------------------------------------------------
#define FA_QS    0                        // Q: 128 x 136 halves
#define FA_KS    17408                    // K: 3 x 64 x 72
#define FA_VS    31232                    // V: 3 x 64 x 72
#define FA_MB_B  90112                    // bitmap: 64 u32
#define FA_FLG_B 90368                    // flags: 32 int
#define FA_SMEM  90496

__global__ void __launch_bounds__(256, 2)
flash_attn(const __half* __restrict__ Qh, const __half* __restrict__ Ql,
           const __half* __restrict__ Kh, const __half* __restrict__ Vh,
           const int* __restrict__ mask, __half* __restrict__ Ch)
{
    extern __shared__ __align__(16) __half sm[];
    __half* Qs = sm + FA_QS;
    __half* Ks = sm + FA_KS;
    __half* Vs = sm + FA_VS;
    uint32_t* mb = (uint32_t*)((char*)sm + FA_MB_B);
    int* flg = (int*)((char*)sm + FA_FLG_B);

    const int tid = threadIdx.x, lane = tid & 31, w = tid >> 5;
    const int qb = blockIdx.x, z = blockIdx.y;
    const int b = z >> 4, h = z & 15;

    const __half* Qhp = Qh + ((size_t)(b * SEQ + qb * 128)) * DM + h * HD;
    const __half* Qlp = Ql + ((size_t)(b * SEQ + qb * 128)) * DM + h * HD;
    const __half* Khp = Kh + ((size_t)(b * SEQ)) * DM + h * HD;
    const __half* Vhp = Vh + (size_t)z * HD * SEQ;

    if (tid < 32) flg[tid] = 0;
    __syncthreads();
    #pragma unroll
    for (int i = 0; i < 8; i++) {
        int k = i * 256 + tid;
        int m = mask[b * SEQ + k];
        uint32_t bits = __ballot_sync(0xffffffffu, m != 0);
        if (lane == 0) {
            mb[k >> 5] = bits;
            if (bits != 0xffffffffu) flg[k >> 6] = 1;
        }
    }

    // Q tile: 128 rows x (64 hi | 64 lo)
    {
        int r = tid >> 1, q = tid & 1;
        #pragma unroll
        for (int i = 0; i < 4; i++) {
            int cc = (q + i * 2) * 8;
            CPASYNC(su32(Qs + r * 136 + cc),      Qhp + (size_t)r * DM + cc);
            CPASYNC(su32(Qs + r * 136 + 64 + cc), Qlp + (size_t)r * DM + cc);
        }
    }
    auto loadKV = [&](int kb, int st) {
        int r = tid >> 2, q = tid & 3;
        #pragma unroll
        for (int i = 0; i < 2; i++) {
            int cc = (q + i * 4) * 8;
            CPASYNC(su32(Ks + st * 4608 + r * 72 + cc),
                    Khp + (size_t)(kb * 64 + r) * DM + cc);
            CPASYNC(su32(Vs + st * 4608 + r * 72 + cc),
                    Vhp + (size_t)r * SEQ + kb * 64 + cc);
        }
    };
    loadKV(0, 0); CPCOMMIT();
    loadKV(1, 1); CPCOMMIT();

    const int frow = ((lane >> 3) & 1) * 8 + (lane & 7);
    const int fcol = ((lane >> 4) & 1) * 8;
    const int er = lane >> 2, ec = (lane & 3) * 2;

    float Oa[8][4];
    #pragma unroll
    for (int j = 0; j < 8; j++)
        #pragma unroll
        for (int t = 0; t < 4; t++) Oa[j][t] = 0.f;
    float mrow[2] = { -1e30f, -1e30f }, lrow[2] = { 0.f, 0.f };

    int st = 0;
    for (int kb = 0; kb < 32; kb++) {
        if (kb + 2 < 32) {
            int stl = st + 2; if (stl >= 3) stl -= 3;
            loadKV(kb + 2, stl); CPCOMMIT(); CPWAIT2();
        } else if (kb + 1 < 32) {
            CPWAIT1();
        } else {
            CPWAIT0();
        }
        __syncthreads();

        // ---- S = Qh·Kh + Ql·Kh (16 x 64 per warp, exp2 domain) ----
        float Sa[8][4];
        #pragma unroll
        for (int j = 0; j < 8; j++)
            #pragma unroll
            for (int t = 0; t < 4; t++) Sa[j][t] = 0.f;

        const __half* kbuf = Ks + st * 4608;
        #pragma unroll
        for (int k = 0; k < 4; k++) {
            uint32_t qhf[4], qlf[4];
            ldm4(qhf, su32(Qs + (w * 16 + frow) * 136 + k * 16 + fcol));
            ldm4(qlf, su32(Qs + (w * 16 + frow) * 136 + 64 + k * 16 + fcol));
            #pragma unroll
            for (int j = 0; j < 4; j++) {
                uint32_t b4[4];
                ldm4(b4, su32(kbuf + (j * 16 + frow) * 72 + k * 16 + fcol));
                mma16816(Sa[2 * j],     qhf, b4[0], b4[2]);
                mma16816(Sa[2 * j + 1], qhf, b4[1], b4[3]);
                mma16816(Sa[2 * j],     qlf, b4[0], b4[2]);
                mma16816(Sa[2 * j + 1], qlf, b4[1], b4[3]);
            }
        }

        // ---- mask (bitmap) ----
        if (flg[kb]) {
            #pragma unroll
            for (int j = 0; j < 8; j++) {
                int c0 = kb * 64 + j * 8 + ec;
                if (!((mb[c0 >> 5] >> (c0 & 31)) & 1u))         { Sa[j][0] = -1e9f; Sa[j][2] = -1e9f; }
                if (!((mb[(c0+1) >> 5] >> ((c0+1) & 31)) & 1u)) { Sa[j][1] = -1e9f; Sa[j][3] = -1e9f; }
            }
        }

        // ---- online softmax: max + exp2 (rows er, er+8) ----
        float mx0 = -1e30f, mx1 = -1e30f;
        #pragma unroll
        for (int j = 0; j < 8; j++) {
            mx0 = fmaxf(mx0, fmaxf(Sa[j][0], Sa[j][1]));
            mx1 = fmaxf(mx1, fmaxf(Sa[j][2], Sa[j][3]));
        }
        #pragma unroll
        for (int o = 1; o <= 2; o <<= 1) {
            mx0 = fmaxf(mx0, __shfl_xor_sync(0xffffffffu, mx0, o));
            mx1 = fmaxf(mx1, __shfl_xor_sync(0xffffffffu, mx1, o));
        }
        float nm0 = fmaxf(mrow[0], mx0), nm1 = fmaxf(mrow[1], mx1);
        float cor0 = ex2(mrow[0] - nm0), cor1 = ex2(mrow[1] - nm1);
        mrow[0] = nm0; mrow[1] = nm1;

        #pragma unroll
        for (int j = 0; j < 8; j++) {
            Sa[j][0] = ex2(Sa[j][0] - nm0);
            Sa[j][1] = ex2(Sa[j][1] - nm0);
            Sa[j][2] = ex2(Sa[j][2] - nm1);
            Sa[j][3] = ex2(Sa[j][3] - nm1);
        }

        // ---- rescale O only if some row max moved (warp-uniform check) ----
        bool nochg = __all_sync(0xffffffffu, (cor0 == 1.f) && (cor1 == 1.f));
        if (!nochg) {
            #pragma unroll
            for (int j = 0; j < 8; j++) {
                Oa[j][0] *= cor0; Oa[j][1] *= cor0;
                Oa[j][2] *= cor1; Oa[j][3] *= cor1;
            }
        }

        // ---- PV: O += Ph·Vh ----
        const __half* vbuf = Vs + st * 4608;
        #pragma unroll
        for (int c = 0; c < 4; c++) {
            uint32_t ph[4];
            ph[0] = pk2(Sa[2*c][0],   Sa[2*c][1]);
            ph[1] = pk2(Sa[2*c][2],   Sa[2*c][3]);
            ph[2] = pk2(Sa[2*c+1][0], Sa[2*c+1][1]);
            ph[3] = pk2(Sa[2*c+1][2], Sa[2*c+1][3]);
            #pragma unroll
            for (int t = 0; t < 4; t++) {
                uint32_t v4[4];
                ldm4(v4, su32(vbuf + (t * 16 + frow) * 72 + c * 16 + fcol));
                mma16816(Oa[2 * t],     ph, v4[0], v4[2]);
                mma16816(Oa[2 * t + 1], ph, v4[1], v4[3]);
            }
        }

        // ---- l-sum after PV (latency hidden under MMAs) ----
        float rs0 = 0.f, rs1 = 0.f;
        #pragma unroll
        for (int j = 0; j < 8; j++) {
            rs0 += Sa[j][0] + Sa[j][1];
            rs1 += Sa[j][2] + Sa[j][3];
        }
        #pragma unroll
        for (int o = 1; o <= 2; o <<= 1) {
            rs0 += __shfl_xor_sync(0xffffffffu, rs0, o);
            rs1 += __shfl_xor_sync(0xffffffffu, rs1, o);
        }
        if (nochg) { lrow[0] += rs0;              lrow[1] += rs1; }
        else       { lrow[0] = lrow[0] * cor0 + rs0; lrow[1] = lrow[1] * cor1 + rs1; }

        __syncthreads();
        if (++st >= 3) st = 0;
    }

    // ---- epilogue: normalize, write ctx fp16 ----
    float i0 = 1.f / lrow[0], i1 = 1.f / lrow[1];
    int r0g = b * SEQ + qb * 128 + w * 16 + er;
    size_t base0 = (size_t)r0g * DM + h * HD;
    size_t base1 = base0 + (size_t)8 * DM;
    #pragma unroll
    for (int j = 0; j < 8; j++) {
        int d0 = j * 8 + ec;
        *(uint32_t*)(Ch + base0 + d0) = pk2(Oa[j][0] * i0, Oa[j][1] * i0);
        *(uint32_t*)(Ch + base1 + d0) = pk2(Oa[j][2] * i1, Oa[j][3] * i1);
    }
}

// ---------------------------------------------------------------------------
extern "C" void kernel_launch(void* const* d_in, const int* in_sizes, int n_in,
                              void* d_out, int out_size)
{
    const float* query = (const float*)d_in[0];
    const float* key   = (const float*)d_in[1];
    const float* value = (const float*)d_in[2];
    const int*   mask  = (const int*)d_in[3];
    const float* wq = (const float*)d_in[4];  const float* bq = (const float*)d_in[5];
    const float* wk = (const float*)d_in[6];  const float* bk = (const float*)d_in[7];
    const float* wv = (const float*)d_in[8];  const float* bv = (const float*)d_in[9];
    const float* wo = (const float*)d_in[10]; const float* bo = (const float*)d_in[11];

    #define SYM(p, sname) void* p; cudaGetSymbolAddress(&p, sname)
    SYM(xh, g_xh); SYM(wh, g_wh);
    SYM(qh, g_qh); SYM(ql, g_ql); SYM(kh, g_kh); SYM(vth, g_vth);
    SYM(ch, g_ch);
    #undef SYM
    typedef __half hf;

    const int GEMM_SMEM = 3 * 2 * GPL * (int)sizeof(hf);   // 61440 (ah+bh x3)
    static bool init = false;
    if (!init) {
        cudaFuncSetAttribute(flash_attn, cudaFuncAttributeMaxDynamicSharedMemorySize,
                             FA_SMEM);
        cudaFuncSetAttribute(gemm_fp16<1>, cudaFuncAttributeMaxDynamicSharedMemorySize,
                             GEMM_SMEM);
        cudaFuncSetAttribute(gemm_fp16<0>, cudaFuncAttributeMaxDynamicSharedMemorySize,
                             GEMM_SMEM);
        init = true;
    }

    // 1) convert inputs + weights to fp16 (one fused launch)
    conv_all<<<dim3(NELEM / 4 / 256, 7), 256>>>(
        (const float4*)query, (const float4*)key, (const float4*)value,
        (const float4*)wq, (const float4*)wk, (const float4*)wv, (const float4*)wo,
        (uint2*)xh, (uint2*)wh);

    // 2) Q/K/V projections (1-term)
    gemm_fp16<1><<<dim3(8, 32, 3), 256, GEMM_SMEM>>>(
        (hf*)xh, (hf*)wh, bq, bk, bv,
        nullptr, (hf*)qh, (hf*)ql, (hf*)kh, (hf*)vth);

    // 3) fused flash attention
    flash_attn<<<dim3(SEQ / 128, ZH), 256, FA_SMEM>>>(
        (hf*)qh, (hf*)ql, (hf*)kh, (hf*)vth, mask, (hf*)ch);

    // 4) output projection (1-term ctx)
    gemm_fp16<0><<<dim3(8, 32, 1), 256, GEMM_SMEM>>>(
        (hf*)ch, (hf*)wh + 3 * (size_t)WELEM, bo, nullptr, nullptr,
        (float*)d_out, nullptr, nullptr, nullptr, nullptr);
}